// round 1
// baseline (speedup 1.0000x reference)
#include <cuda_runtime.h>
#include <math.h>
#include <stdint.h>

// Shapes fixed by the problem: [16, 1, 1024, 1024] float32
#define BB 16
#define HH 1024
#define WW 1024
#define NPIX (BB * HH * WW)          // 16777216
#define NBLK 16384                    // (1024/32)*(1024/32)*16 tiles
#define TS 36                         // smem tile row stride (34 used + pad)

// ---------------- device scratch (static; no allocation at runtime) ----------
__device__ uint8_t g_binP[NPIX];      // binary(pred_prob) — preserved for Sobel, iter-0 input
__device__ uint8_t g_binT[NPIX];      // binary(target)
__device__ uint8_t g_wp0[NPIX];       // skeleton ping-pong (pred)
__device__ uint8_t g_wp1[NPIX];
__device__ uint8_t g_wt0[NPIX];       // skeleton ping-pong (target)
__device__ uint8_t g_wt1[NPIX];

__device__ double g_partA[6 * NBLK];  // main-pass partials: Sp,St,Spt,Sfocal,Sconn,nwater
__device__ double g_partF[3 * NBLK];  // finalize partials: SfP,SfT,SfPfT

__device__ unsigned long long g_curr[2];   // running skeleton sums (P,T)
__device__ unsigned long long g_prev[2];
__device__ int g_done[2];
__device__ int g_last[2];             // which ping-pong buffer holds the final skel (1->wp0,2->wp1)
__device__ double g_sums[9];

// ---------------- helpers ----------------------------------------------------
__device__ __forceinline__ float blockReduce256f(float v, float* sm) {
    int tid = threadIdx.y * 32 + threadIdx.x;
    sm[tid] = v; __syncthreads();
#pragma unroll
    for (int s = 128; s > 0; s >>= 1) {
        if (tid < s) sm[tid] += sm[tid + s];
        __syncthreads();
    }
    float r = sm[0]; __syncthreads();
    return r;
}

// ---------------- init -------------------------------------------------------
__global__ void initKernel() {
    g_curr[0] = g_curr[1] = 0ULL;
    g_prev[0] = g_prev[1] = 0xFFFFFFFFFFFFFFFFULL;  // "inf" sentinel
    g_done[0] = g_done[1] = 0;
    g_last[0] = g_last[1] = 1;
}

// ---------------- pass 1: fused elementwise + connectivity conv --------------
__global__ __launch_bounds__(256) void mainKernel(const float* __restrict__ pred,
                                                  const float* __restrict__ target) {
    __shared__ float sP[34 * TS];
    __shared__ float sT[34 * TS];
    __shared__ float red[256];

    const int img = blockIdx.z;
    const int bx = blockIdx.x * 32, by = blockIdx.y * 32;
    const int tid = threadIdx.y * 32 + threadIdx.x;
    const float* pimg = pred + (long)img * HH * WW;
    const float* timg = target + (long)img * HH * WW;

    // cooperative halo load (zero padding outside the image == conv SAME)
    for (int i = tid; i < 34 * 34; i += 256) {
        int ly = i / 34, lx = i % 34;
        int gy = by - 1 + ly, gx = bx - 1 + lx;
        float pv = 0.f, tv = 0.f;
        if (gy >= 0 && gy < HH && gx >= 0 && gx < WW) {
            float x = pimg[gy * WW + gx];
            pv = 1.0f / (1.0f + expf(-x));   // sigmoid
            tv = timg[gy * WW + gx];
        }
        sP[ly * TS + lx] = pv;
        sT[ly * TS + lx] = tv;
    }
    __syncthreads();

    float a0 = 0.f, a1 = 0.f, a2 = 0.f, a3 = 0.f, a4 = 0.f, a5 = 0.f;
#pragma unroll
    for (int k = 0; k < 4; k++) {
        int y = threadIdx.y + 8 * k;
        int x = threadIdx.x;
        float p = sP[(y + 1) * TS + x + 1];
        float t = sT[(y + 1) * TS + x + 1];

        uint8_t bp = (p > 0.5f) ? 1 : 0;
        uint8_t bt = (t > 0.5f) ? 1 : 0;
        long gidx = (long)img * HH * WW + (long)(by + y) * WW + (bx + x);
        g_binP[gidx] = bp;
        g_binT[gidx] = bt;

        a0 += p;        // sum pred_prob
        a1 += t;        // sum target
        a2 += p * t;    // sum pred_prob*target

        // focal (gamma=2, alpha=0.25)
        float pc = fminf(fmaxf(p, 1e-6f), 1.0f - 1e-6f);
        float bce = -(t * logf(pc) + (1.0f - t) * logf(1.0f - pc));
        float pt = (t == 1.0f) ? pc : (1.0f - pc);
        float fw = (1.0f - pt) * (1.0f - pt);
        float at = (t == 1.0f) ? 0.25f : 0.75f;
        a3 += at * fw * bce;

        // connectivity: (conv3(p - t, ones)/9)^2 * wmask
        float ds = 0.f;
#pragma unroll
        for (int dy = 0; dy < 3; dy++)
#pragma unroll
            for (int dx = 0; dx < 3; dx++)
                ds += sP[(y + dy) * TS + x + dx] - sT[(y + dy) * TS + x + dx];
        float v = ds * (1.0f / 9.0f);
        if (bt) { a4 += v * v; a5 += 1.0f; }
    }

    int bid = (blockIdx.z * gridDim.y + blockIdx.y) * gridDim.x + blockIdx.x;
    float r;
    r = blockReduce256f(a0, red); if (tid == 0) g_partA[0 * NBLK + bid] = (double)r;
    r = blockReduce256f(a1, red); if (tid == 0) g_partA[1 * NBLK + bid] = (double)r;
    r = blockReduce256f(a2, red); if (tid == 0) g_partA[2 * NBLK + bid] = (double)r;
    r = blockReduce256f(a3, red); if (tid == 0) g_partA[3 * NBLK + bid] = (double)r;
    r = blockReduce256f(a4, red); if (tid == 0) g_partA[4 * NBLK + bid] = (double)r;
    r = blockReduce256f(a5, red); if (tid == 0) g_partA[5 * NBLK + bid] = (double)r;
}

// ---------------- skeleton iteration (P and T fused; uint8 state) ------------
// state closed over {0,1,2}: e = (sum3x3 >= 9); out = e ? (c==1 ? 2 : 1) : 0
__global__ __launch_bounds__(256) void iterKernel(int src, int dst) {
    __shared__ int tile[34 * TS];
    __shared__ int redI[256];

    const int z = blockIdx.z;
    const int which = (z >= 16) ? 1 : 0;
    if (g_done[which]) return;          // uniform per block -> safe early exit
    const int img = z & 15;

    const uint8_t* in;
    uint8_t* out;
    if (which == 0) {
        in = (src == 0) ? g_binP : ((src == 1) ? g_wp0 : g_wp1);
        out = (dst == 1) ? g_wp0 : g_wp1;
    } else {
        in = (src == 0) ? g_binT : ((src == 1) ? g_wt0 : g_wt1);
        out = (dst == 1) ? g_wt0 : g_wt1;
    }

    const int bx = blockIdx.x * 32, by = blockIdx.y * 32;
    const int tid = threadIdx.y * 32 + threadIdx.x;
    const uint8_t* inimg = in + (long)img * HH * WW;

    for (int i = tid; i < 34 * 34; i += 256) {
        int ly = i / 34, lx = i % 34;
        int gy = by - 1 + ly, gx = bx - 1 + lx;
        int v = 0;
        if (gy >= 0 && gy < HH && gx >= 0 && gx < WW) v = inimg[gy * WW + gx];
        tile[ly * TS + lx] = v;
    }
    __syncthreads();

    int acc = 0;
#pragma unroll
    for (int k = 0; k < 4; k++) {
        int y = threadIdx.y + 8 * k;
        int x = threadIdx.x;
        int c = tile[(y + 1) * TS + x + 1];
        int s = 0;
#pragma unroll
        for (int dy = 0; dy < 3; dy++)
#pragma unroll
            for (int dx = 0; dx < 3; dx++)
                s += tile[(y + dy) * TS + x + dx];
        int o = (s >= 9) ? ((c == 1) ? 2 : 1) : 0;
        long gidx = (long)img * HH * WW + (long)(by + y) * WW + (bx + x);
        out[gidx] = (uint8_t)o;
        acc += o;
    }

    redI[tid] = acc; __syncthreads();
#pragma unroll
    for (int s = 128; s > 0; s >>= 1) {
        if (tid < s) redI[tid] += redI[tid + s];
        __syncthreads();
    }
    if (tid == 0) atomicAdd(&g_curr[which], (unsigned long long)redI[0]);
}

__global__ void flagKernel(int dst) {
    for (int w = 0; w < 2; w++) {
        if (!g_done[w]) {
            if (g_curr[w] == g_prev[w]) g_done[w] = 1;  // |curr-prev| < 1 exactly (ints)
            g_prev[w] = g_curr[w];
            g_last[w] = dst;
        }
        g_curr[w] = 0ULL;
    }
}

// ---------------- finalize: Sobel edges + skeleton dice sums -----------------
__global__ __launch_bounds__(256) void finKernel() {
    __shared__ int tP[34 * TS];
    __shared__ int tT[34 * TS];
    __shared__ float red[256];

    const int img = blockIdx.z;
    const int bx = blockIdx.x * 32, by = blockIdx.y * 32;
    const int tid = threadIdx.y * 32 + threadIdx.x;
    const uint8_t* bP = g_binP + (long)img * HH * WW;
    const uint8_t* bT = g_binT + (long)img * HH * WW;
    const uint8_t* sp = (g_last[0] == 1) ? g_wp0 : g_wp1;
    const uint8_t* st = (g_last[1] == 1) ? g_wt0 : g_wt1;

    for (int i = tid; i < 34 * 34; i += 256) {
        int ly = i / 34, lx = i % 34;
        int gy = by - 1 + ly, gx = bx - 1 + lx;
        int vp = 0, vt = 0;
        if (gy >= 0 && gy < HH && gx >= 0 && gx < WW) {
            vp = bP[gy * WW + gx];
            vt = bT[gy * WW + gx];
        }
        tP[ly * TS + lx] = vp;
        tT[ly * TS + lx] = vt;
    }
    __syncthreads();

    float a0 = 0.f, a1 = 0.f, a2 = 0.f;
#pragma unroll
    for (int k = 0; k < 4; k++) {
        int y = threadIdx.y + 8 * k;
        int x = threadIdx.x;
        long gidx = (long)img * HH * WW + (long)(by + y) * WW + (bx + x);

        // Sobel (sign irrelevant: squared)
        int gxP = (tP[y*TS + x+2] + 2*tP[(y+1)*TS + x+2] + tP[(y+2)*TS + x+2])
                - (tP[y*TS + x  ] + 2*tP[(y+1)*TS + x  ] + tP[(y+2)*TS + x  ]);
        int gyP = (tP[(y+2)*TS + x] + 2*tP[(y+2)*TS + x+1] + tP[(y+2)*TS + x+2])
                - (tP[y*TS + x    ] + 2*tP[y*TS + x+1    ] + tP[y*TS + x+2  ]);
        int gxT = (tT[y*TS + x+2] + 2*tT[(y+1)*TS + x+2] + tT[(y+2)*TS + x+2])
                - (tT[y*TS + x  ] + 2*tT[(y+1)*TS + x  ] + tT[(y+2)*TS + x  ]);
        int gyT = (tT[(y+2)*TS + x] + 2*tT[(y+2)*TS + x+1] + tT[(y+2)*TS + x+2])
                - (tT[y*TS + x    ] + 2*tT[y*TS + x+1    ] + tT[y*TS + x+2  ]);

        float eP = sqrtf((float)(gxP * gxP + gyP * gyP) + 1e-8f);
        float eT = sqrtf((float)(gxT * gxT + gyT * gyT) + 1e-8f);
        float fP = fminf(1.0f, (float)sp[gidx] + 0.5f * eP);
        float fT = fminf(1.0f, (float)st[gidx] + 0.5f * eT);
        a0 += fP; a1 += fT; a2 += fP * fT;
    }

    int bid = (blockIdx.z * gridDim.y + blockIdx.y) * gridDim.x + blockIdx.x;
    float r;
    r = blockReduce256f(a0, red); if (tid == 0) g_partF[0 * NBLK + bid] = (double)r;
    r = blockReduce256f(a1, red); if (tid == 0) g_partF[1 * NBLK + bid] = (double)r;
    r = blockReduce256f(a2, red); if (tid == 0) g_partF[2 * NBLK + bid] = (double)r;
}

// ---------------- deterministic cross-block reductions -----------------------
__global__ void reduceAKernel() {
    __shared__ double sm[256];
    int tid = threadIdx.x;
    for (int q = 0; q < 6; q++) {
        double s = 0.0;
        for (int i = tid; i < NBLK; i += 256) s += g_partA[q * NBLK + i];
        sm[tid] = s; __syncthreads();
        for (int st = 128; st > 0; st >>= 1) {
            if (tid < st) sm[tid] += sm[tid + st];
            __syncthreads();
        }
        if (tid == 0) g_sums[q] = sm[0];
        __syncthreads();
    }
}

__global__ void reduceFKernel() {
    __shared__ double sm[256];
    int tid = threadIdx.x;
    for (int q = 0; q < 3; q++) {
        double s = 0.0;
        for (int i = tid; i < NBLK; i += 256) s += g_partF[q * NBLK + i];
        sm[tid] = s; __syncthreads();
        for (int st = 128; st > 0; st >>= 1) {
            if (tid < st) sm[tid] += sm[tid + st];
            __syncthreads();
        }
        if (tid == 0) g_sums[6 + q] = sm[0];
        __syncthreads();
    }
}

// ---------------- final scalar math ------------------------------------------
__global__ void finalKernel(float* out) {
    double Sp  = g_sums[0], St = g_sums[1], Spt = g_sums[2];
    double Sf  = g_sums[3], Sc = g_sums[4], nw  = g_sums[5];
    double S6  = g_sums[6], S7 = g_sums[7], S8  = g_sums[8];

    double skel_dice = (2.0 * S8 + 1.0) / (S6 + S7 + 1.0);
    double skeleton = 1.0 - skel_dice;
    double dice = 1.0 - (2.0 * Spt + 1.0) / (Sp + St + 1.0);
    double focal = Sf / (double)NPIX;
    focal = fmin(fmax(focal, 0.0), 10.0);
    double conn = (nw == 0.0) ? 0.0 : (Sc / fmax(nw, 1.0));

    double total = 0.3 * skeleton + 0.4 * dice + 0.2 * focal + 0.1 * conn;
    if (isnan(total) || isinf(total)) total = dice;
    out[0] = (float)total;
}

// ---------------- launch -----------------------------------------------------
extern "C" void kernel_launch(void* const* d_in, const int* in_sizes, int n_in,
                              void* d_out, int out_size) {
    const float* pred = (const float*)d_in[0];
    const float* target = (const float*)d_in[1];
    float* out = (float*)d_out;

    dim3 blk(32, 8);
    dim3 grdA(32, 32, 16);   // tiles x, tiles y, batch
    dim3 grdI(32, 32, 32);   // z: 0..15 pred-skel, 16..31 target-skel

    initKernel<<<1, 1>>>();
    mainKernel<<<grdA, blk>>>(pred, target);
    reduceAKernel<<<1, 256>>>();

    for (int i = 0; i < 10; i++) {
        int src = (i == 0) ? 0 : ((i % 2 == 0) ? 2 : 1);  // 0=bin, 1=wp0, 2=wp1
        int dst = (i % 2 == 0) ? 1 : 2;
        iterKernel<<<grdI, blk>>>(src, dst);
        flagKernel<<<1, 1>>>(dst);
    }

    finKernel<<<grdA, blk>>>();
    reduceFKernel<<<1, 256>>>();
    finalKernel<<<1, 1>>>(out);
}

// round 2
// speedup vs baseline: 1.9584x; 1.9584x over previous
#include <cuda_runtime.h>
#include <math.h>
#include <stdint.h>

// Shapes fixed by the problem: [16, 1, 1024, 1024] float32
#define BB 16
#define HH 1024
#define WW 1024
#define WPR 256                       // uint32 words per row (1024/4)
#define NPIX (BB * HH * WW)           // 16777216
#define NWORD (NPIX / 4)
#define NBLK_A 16384                  // main grid blocks (32*32*16)
#define NBLK_F 4096                   // fin grid blocks (8*32*16)
#define GRID_I 8192                   // iter grid blocks (8*32*32)
#define TS 36                         // smem row stride (34 used + pad)

// ---------------- device scratch (word-aligned; no runtime allocation) -------
__device__ uint32_t g_binP[NWORD];    // binary(pred_prob), 1 byte/pixel
__device__ uint32_t g_binT[NWORD];    // binary(target)
__device__ uint32_t g_wp0[NWORD];     // skeleton ping-pong (pred)
__device__ uint32_t g_wp1[NWORD];
__device__ uint32_t g_wt0[NWORD];     // skeleton ping-pong (target)
__device__ uint32_t g_wt1[NWORD];

__device__ double g_partA[6 * NBLK_A];
__device__ double g_partF[3 * NBLK_F];

__device__ unsigned long long g_curr[2];
__device__ unsigned long long g_prev[2];
__device__ int g_done[2];
__device__ int g_last[2];             // 1 -> wX0, 2 -> wX1 holds final skeleton
__device__ unsigned int g_count;      // grid arrival counter for iterKernel
__device__ double g_sums[9];

// ---------------- init -------------------------------------------------------
__global__ void initKernel() {
    g_curr[0] = g_curr[1] = 0ULL;
    g_prev[0] = g_prev[1] = 0xFFFFFFFFFFFFFFFFULL;  // "inf" sentinel
    g_done[0] = g_done[1] = 0;
    g_last[0] = g_last[1] = 1;
    g_count = 0;
}

// ---------------- pass 1: fused elementwise + separable connectivity conv ----
__global__ __launch_bounds__(256) void mainKernel(const float* __restrict__ pred,
                                                  const float* __restrict__ target) {
    __shared__ float sP[34 * TS];
    __shared__ float sT[34 * TS];
    __shared__ float sV[32 * TS];     // vertical 3-row sums of (p - t)
    __shared__ float smw[48];         // 8 warps x 6 accumulators

    const int img = blockIdx.z;
    const int bx = blockIdx.x * 32, by = blockIdx.y * 32;
    const int tid = threadIdx.y * 32 + threadIdx.x;
    const float* pimg = pred + (long)img * HH * WW;
    const float* timg = target + (long)img * HH * WW;

    // halo load (zero pad == SAME)
    for (int i = tid; i < 34 * 34; i += 256) {
        int ly = i / 34, lx = i % 34;
        int gy = by - 1 + ly, gx = bx - 1 + lx;
        float pv = 0.f, tv = 0.f;
        if (gy >= 0 && gy < HH && gx >= 0 && gx < WW) {
            float x = pimg[gy * WW + gx];
            pv = 1.0f / (1.0f + expf(-x));
            tv = timg[gy * WW + gx];
        }
        sP[ly * TS + lx] = pv;
        sT[ly * TS + lx] = tv;
    }
    __syncthreads();

    // vertical pass for connectivity conv
    for (int i = tid; i < 32 * 34; i += 256) {
        int r = i / 34, w = i % 34;
        float d0 = sP[r * TS + w] - sT[r * TS + w];
        float d1 = sP[(r + 1) * TS + w] - sT[(r + 1) * TS + w];
        float d2 = sP[(r + 2) * TS + w] - sT[(r + 2) * TS + w];
        sV[r * TS + w] = d0 + d1 + d2;
    }
    __syncthreads();

    float a0 = 0.f, a1 = 0.f, a2 = 0.f, a3 = 0.f, a4 = 0.f, a5 = 0.f;
    uint8_t* bP8 = (uint8_t*)g_binP;
    uint8_t* bT8 = (uint8_t*)g_binT;
#pragma unroll
    for (int k = 0; k < 4; k++) {
        int y = threadIdx.y + 8 * k;
        int x = threadIdx.x;
        float p = sP[(y + 1) * TS + x + 1];
        float t = sT[(y + 1) * TS + x + 1];

        uint8_t bp = (p > 0.5f) ? 1 : 0;
        uint8_t bt = (t > 0.5f) ? 1 : 0;
        long gidx = (long)img * HH * WW + (long)(by + y) * WW + (bx + x);
        bP8[gidx] = bp;
        bT8[gidx] = bt;

        a0 += p;
        a1 += t;
        a2 += p * t;

        // focal (gamma=2, alpha=0.25) — exact formulation as R1 (passed)
        float pc = fminf(fmaxf(p, 1e-6f), 1.0f - 1e-6f);
        float bce = -(t * logf(pc) + (1.0f - t) * logf(1.0f - pc));
        float pt = (t == 1.0f) ? pc : (1.0f - pc);
        float fw = (1.0f - pt) * (1.0f - pt);
        float at = (t == 1.0f) ? 0.25f : 0.75f;
        a3 += at * fw * bce;

        // connectivity: (conv3(p - t, ones)/9)^2 * (t > .5)
        float ds = sV[y * TS + x] + sV[y * TS + x + 1] + sV[y * TS + x + 2];
        float v = ds * (1.0f / 9.0f);
        if (bt) { a4 += v * v; a5 += 1.0f; }
    }

    // warp-shuffle reduction, single barrier
    float vals[6] = {a0, a1, a2, a3, a4, a5};
    int lane = threadIdx.x;
    int wrp = tid >> 5;
#pragma unroll
    for (int q = 0; q < 6; q++) {
        float v = vals[q];
#pragma unroll
        for (int o = 16; o > 0; o >>= 1) v += __shfl_xor_sync(0xFFFFFFFFu, v, o);
        if (lane == 0) smw[wrp * 6 + q] = v;
    }
    __syncthreads();
    int bid = (blockIdx.z * gridDim.y + blockIdx.y) * gridDim.x + blockIdx.x;
    if (tid < 6) {
        double s = 0.0;
        for (int w = 0; w < 8; w++) s += (double)smw[w * 6 + tid];
        g_partA[tid * NBLK_A + bid] = s;
    }
}

// ---------------- skeleton iteration: SWAR, 4 pixels/word --------------------
// state closed over {0,1,2}: e = (sum3x3 >= 9); out = e ? (c==1 ? 2 : 1) : 0
__device__ __forceinline__ void iterArrive(int dst) {
    __threadfence();
    unsigned int old = atomicInc(&g_count, GRID_I - 1);
    if (old == GRID_I - 1) {   // last block: fold the old flagKernel in here
        for (int w = 0; w < 2; w++) {
            if (!g_done[w]) {
                if (g_curr[w] == g_prev[w]) g_done[w] = 1;   // ints: |d|<1 <=> equal
                g_prev[w] = g_curr[w];
                g_last[w] = dst;
            }
            g_curr[w] = 0ULL;
        }
    }
}

__global__ __launch_bounds__(256) void iterKernel(int src, int dst) {
    __shared__ uint32_t raw[34 * TS];
    __shared__ uint32_t V[32 * TS];
    __shared__ int smi[8];

    const int z = blockIdx.z;
    const int which = z >> 4;
    const int img = z & 15;
    const int tid = threadIdx.y * 32 + threadIdx.x;

    if (g_done[which]) {               // frozen: just participate in arrival
        if (tid == 0) iterArrive(dst);
        return;
    }

    const uint32_t *in32;
    uint32_t *out32;
    if (which == 0) {
        in32 = (src == 0) ? g_binP : ((src == 1) ? g_wp0 : g_wp1);
        out32 = (dst == 1) ? g_wp0 : g_wp1;
    } else {
        in32 = (src == 0) ? g_binT : ((src == 1) ? g_wt0 : g_wt1);
        out32 = (dst == 1) ? g_wt0 : g_wt1;
    }
    in32 += (long)img * (HH * WPR);
    out32 += (long)img * (HH * WPR);

    const int bw = blockIdx.x * 32;    // word column base
    const int by = blockIdx.y * 32;

    for (int i = tid; i < 34 * 34; i += 256) {
        int lr = i / 34, lw = i % 34;
        int gy = by - 1 + lr, gw = bw - 1 + lw;
        uint32_t v = 0;
        if (gy >= 0 && gy < HH && gw >= 0 && gw < WPR) v = in32[gy * WPR + gw];
        raw[lr * TS + lw] = v;
    }
    __syncthreads();

    for (int i = tid; i < 32 * 34; i += 256) {
        int r = i / 34, w = i % 34;
        V[r * TS + w] = raw[r * TS + w] + raw[(r + 1) * TS + w] + raw[(r + 2) * TS + w];
    }
    __syncthreads();

    int acc = 0;
#pragma unroll
    for (int k = 0; k < 4; k++) {
        int y = threadIdx.y + 8 * k;
        int si = y * TS + threadIdx.x;
        uint32_t Vl = V[si], Vc = V[si + 1], Vr = V[si + 2];
        uint32_t H = Vc + ((Vc >> 8) | (Vr << 24)) + ((Vc << 8) | (Vl >> 24));
        uint32_t c = raw[(y + 1) * TS + threadIdx.x + 1];
        uint32_t ge = __vcmpgeu4(H, 0x09090909u);
        uint32_t eq1 = __vcmpeq4(c, 0x01010101u);
        uint32_t o = (ge & 0x01010101u) + (ge & eq1 & 0x01010101u);
        out32[(by + y) * WPR + bw + threadIdx.x] = o;
        acc = __dp4a(o, 0x01010101u, (unsigned int)acc);
    }

#pragma unroll
    for (int o = 16; o > 0; o >>= 1) acc += __shfl_xor_sync(0xFFFFFFFFu, acc, o);
    if (threadIdx.x == 0) smi[tid >> 5] = acc;
    __syncthreads();
    if (tid == 0) {
        int s = 0;
        for (int w = 0; w < 8; w++) s += smi[w];
        atomicAdd(&g_curr[which], (unsigned long long)s);
        iterArrive(dst);
    }
}

// ---------------- finalize: SWAR Sobel + skeleton dice sums ------------------
// On binary input |gx|,|gy| <= 4, so f = clip(skel + .5*sqrt(gx^2+gy^2+1e-8),0,1)
// quantizes: f = 1 if skel>=1 or g2>=4 else {0:5e-5, 1:.5, 2:.7071, 3:.8660}[g2]
__global__ __launch_bounds__(256) void finKernel() {
    __shared__ uint32_t rawP[34 * TS];
    __shared__ uint32_t rawT[34 * TS];
    __shared__ uint32_t AP[32 * TS], BP[32 * TS];
    __shared__ uint32_t AT[32 * TS], BT[32 * TS];
    __shared__ float smw[24];

    const int img = blockIdx.z;
    const int tid = threadIdx.y * 32 + threadIdx.x;
    const int bw = blockIdx.x * 32;
    const int by = blockIdx.y * 32;

    const uint32_t* bP = g_binP + (long)img * (HH * WPR);
    const uint32_t* bT = g_binT + (long)img * (HH * WPR);
    const uint32_t* sp = ((g_last[0] == 1) ? g_wp0 : g_wp1) + (long)img * (HH * WPR);
    const uint32_t* st = ((g_last[1] == 1) ? g_wt0 : g_wt1) + (long)img * (HH * WPR);

    for (int i = tid; i < 34 * 34; i += 256) {
        int lr = i / 34, lw = i % 34;
        int gy = by - 1 + lr, gw = bw - 1 + lw;
        uint32_t vp = 0, vt = 0;
        if (gy >= 0 && gy < HH && gw >= 0 && gw < WPR) {
            vp = bP[gy * WPR + gw];
            vt = bT[gy * WPR + gw];
        }
        rawP[lr * TS + lw] = vp;
        rawT[lr * TS + lw] = vt;
    }
    __syncthreads();

    // vertical partials: A = r0 + 2*r1 + r2 (<=4/byte), B = r2 - r0 + 1 (0..2/byte)
    for (int i = tid; i < 32 * 34; i += 256) {
        int r = i / 34, w = i % 34;
        uint32_t p0 = rawP[r * TS + w], p1 = rawP[(r + 1) * TS + w], p2 = rawP[(r + 2) * TS + w];
        AP[r * TS + w] = p0 + p1 + p1 + p2;
        BP[r * TS + w] = p2 + (0x01010101u - p0);
        uint32_t t0 = rawT[r * TS + w], t1 = rawT[(r + 1) * TS + w], t2 = rawT[(r + 2) * TS + w];
        AT[r * TS + w] = t0 + t1 + t1 + t2;
        BT[r * TS + w] = t2 + (0x01010101u - t0);
    }
    __syncthreads();

    float a0 = 0.f, a1 = 0.f, a2 = 0.f;
#pragma unroll
    for (int k = 0; k < 4; k++) {
        int y = threadIdx.y + 8 * k;
        int si = y * TS + threadIdx.x;
        // Hx bytes = gx + 4 in [0,8]; Hy bytes = gy + 4 in [0,8]
        uint32_t Al = AP[si], Ac = AP[si + 1], Ar = AP[si + 2];
        uint32_t Bl = BP[si], Bc = BP[si + 1], Br = BP[si + 2];
        uint32_t HxP = (((Ac >> 8) | (Ar << 24)) + (0x04040404u - ((Ac << 8) | (Al >> 24))));
        uint32_t HyP = (((Bc << 8) | (Bl >> 24)) + Bc + Bc + ((Bc >> 8) | (Br << 24)));
        Al = AT[si]; Ac = AT[si + 1]; Ar = AT[si + 2];
        Bl = BT[si]; Bc = BT[si + 1]; Br = BT[si + 2];
        uint32_t HxT = (((Ac >> 8) | (Ar << 24)) + (0x04040404u - ((Ac << 8) | (Al >> 24))));
        uint32_t HyT = (((Bc << 8) | (Bl >> 24)) + Bc + Bc + ((Bc >> 8) | (Br << 24)));

        long widx = (long)(by + y) * WPR + bw + threadIdx.x;
        uint32_t SP = sp[widx];
        uint32_t ST = st[widx];

#pragma unroll
        for (int b = 0; b < 4; b++) {
            int s = 8 * b;
            int gxp = (int)((HxP >> s) & 0xFF) - 4;
            int gyp = (int)((HyP >> s) & 0xFF) - 4;
            int g2p = gxp * gxp + gyp * gyp;
            int skp = (int)((SP >> s) & 0xFF);
            float fP = (skp | (g2p >= 4)) ? 1.0f
                     : (g2p == 0 ? 5.0e-5f : (g2p == 1 ? 0.5f
                        : (g2p == 2 ? 0.70710678f : 0.86602540f)));

            int gxt = (int)((HxT >> s) & 0xFF) - 4;
            int gyt = (int)((HyT >> s) & 0xFF) - 4;
            int g2t = gxt * gxt + gyt * gyt;
            int skt = (int)((ST >> s) & 0xFF);
            float fT = (skt | (g2t >= 4)) ? 1.0f
                     : (g2t == 0 ? 5.0e-5f : (g2t == 1 ? 0.5f
                        : (g2t == 2 ? 0.70710678f : 0.86602540f)));

            a0 += fP; a1 += fT; a2 += fP * fT;
        }
    }

    float vals[3] = {a0, a1, a2};
    int lane = threadIdx.x;
    int wrp = tid >> 5;
#pragma unroll
    for (int q = 0; q < 3; q++) {
        float v = vals[q];
#pragma unroll
        for (int o = 16; o > 0; o >>= 1) v += __shfl_xor_sync(0xFFFFFFFFu, v, o);
        if (lane == 0) smw[wrp * 3 + q] = v;
    }
    __syncthreads();
    int bid = (blockIdx.z * gridDim.y + blockIdx.y) * gridDim.x + blockIdx.x;
    if (tid < 3) {
        double sm = 0.0;
        for (int w = 0; w < 8; w++) sm += (double)smw[w * 3 + tid];
        g_partF[tid * NBLK_F + bid] = sm;
    }
}

// ---------------- deterministic cross-block reductions -----------------------
__global__ void reduceAKernel() {
    __shared__ double sm[256];
    int tid = threadIdx.x;
    for (int q = 0; q < 6; q++) {
        double s = 0.0;
        for (int i = tid; i < NBLK_A; i += 256) s += g_partA[q * NBLK_A + i];
        sm[tid] = s; __syncthreads();
        for (int st = 128; st > 0; st >>= 1) {
            if (tid < st) sm[tid] += sm[tid + st];
            __syncthreads();
        }
        if (tid == 0) g_sums[q] = sm[0];
        __syncthreads();
    }
}

__global__ void reduceFKernel() {
    __shared__ double sm[256];
    int tid = threadIdx.x;
    for (int q = 0; q < 3; q++) {
        double s = 0.0;
        for (int i = tid; i < NBLK_F; i += 256) s += g_partF[q * NBLK_F + i];
        sm[tid] = s; __syncthreads();
        for (int st = 128; st > 0; st >>= 1) {
            if (tid < st) sm[tid] += sm[tid + st];
            __syncthreads();
        }
        if (tid == 0) g_sums[6 + q] = sm[0];
        __syncthreads();
    }
}

// ---------------- final scalar math ------------------------------------------
__global__ void finalKernel(float* out) {
    double Sp  = g_sums[0], St = g_sums[1], Spt = g_sums[2];
    double Sf  = g_sums[3], Sc = g_sums[4], nw  = g_sums[5];
    double S6  = g_sums[6], S7 = g_sums[7], S8  = g_sums[8];

    double skel_dice = (2.0 * S8 + 1.0) / (S6 + S7 + 1.0);
    double skeleton = 1.0 - skel_dice;
    double dice = 1.0 - (2.0 * Spt + 1.0) / (Sp + St + 1.0);
    double focal = Sf / (double)NPIX;
    focal = fmin(fmax(focal, 0.0), 10.0);
    double conn = (nw == 0.0) ? 0.0 : (Sc / fmax(nw, 1.0));

    double total = 0.3 * skeleton + 0.4 * dice + 0.2 * focal + 0.1 * conn;
    if (isnan(total) || isinf(total)) total = dice;
    out[0] = (float)total;
}

// ---------------- launch -----------------------------------------------------
extern "C" void kernel_launch(void* const* d_in, const int* in_sizes, int n_in,
                              void* d_out, int out_size) {
    const float* pred = (const float*)d_in[0];
    const float* target = (const float*)d_in[1];
    float* out = (float*)d_out;

    dim3 blk(32, 8);
    dim3 grdA(32, 32, 16);   // 32x32-pixel tiles, batch
    dim3 grdI(8, 32, 32);    // 32-word (128-pixel) tiles; z: 0..15 P, 16..31 T
    dim3 grdF(8, 32, 16);

    initKernel<<<1, 1>>>();
    mainKernel<<<grdA, blk>>>(pred, target);
    reduceAKernel<<<1, 256>>>();

    for (int i = 0; i < 10; i++) {
        int src = (i == 0) ? 0 : ((i % 2 == 0) ? 2 : 1);  // 0=bin, 1=w0, 2=w1
        int dst = (i % 2 == 0) ? 1 : 2;
        iterKernel<<<grdI, blk>>>(src, dst);
    }

    finKernel<<<grdF, blk>>>();
    reduceFKernel<<<1, 256>>>();
    finalKernel<<<1, 1>>>(out);
}

// round 3
// speedup vs baseline: 2.0524x; 1.0480x over previous
#include <cuda_runtime.h>
#include <math.h>
#include <stdint.h>

// Shapes fixed by the problem: [16, 1, 1024, 1024] float32
#define BB 16
#define HH 1024
#define WW 1024
#define WPR 256                       // uint32 words per row (1024/4)
#define NPIX (BB * HH * WW)           // 16777216
#define NWORD (NPIX / 4)
#define NBLK_A 2048                   // main grid blocks (4*32*16)
#define NBLK_F 1024                   // fin grid blocks (64*16)
#define GRID_I 1024                   // iter grid blocks (32*32)

// ---------------- device scratch (no runtime allocation) ---------------------
__device__ uint32_t g_binP[NWORD];    // binary(pred_prob), 1 byte/pixel
__device__ uint32_t g_binT[NWORD];    // binary(target)
__device__ uint32_t g_wp0[NWORD];     // skeleton ping-pong (pred)
__device__ uint32_t g_wp1[NWORD];
__device__ uint32_t g_wt0[NWORD];     // skeleton ping-pong (target)
__device__ uint32_t g_wt1[NWORD];

__device__ double g_partA[6 * NBLK_A];
__device__ double g_partF[3 * NBLK_F];

__device__ unsigned long long g_curr[2];
__device__ unsigned long long g_prev[2];
__device__ int g_done[2];
__device__ int g_last[2];             // 1 -> wX0, 2 -> wX1 holds final skeleton
__device__ unsigned int g_cntI;       // arrival counters (self-reset via wrap)
__device__ unsigned int g_cntA;
__device__ unsigned int g_cntF;
__device__ double g_sums[6];          // Sp,St,Spt,Sfocal,Sconn,nwater

// ---------------- init -------------------------------------------------------
__global__ void initKernel() {
    g_curr[0] = g_curr[1] = 0ULL;
    g_prev[0] = g_prev[1] = 0xFFFFFFFFFFFFFFFFULL;  // "inf" sentinel
    g_done[0] = g_done[1] = 0;
    g_last[0] = g_last[1] = 1;
    g_cntI = 0; g_cntA = 0; g_cntF = 0;
}

__device__ __forceinline__ float sigm(float x) { return 1.0f / (1.0f + expf(-x)); }

// ---------------- pass 1: fused elementwise + connectivity (register sweep) --
__global__ __launch_bounds__(256) void mainKernel(const float* __restrict__ pred,
                                                  const float* __restrict__ target) {
    __shared__ float smw[48];
    __shared__ double smd[256];
    __shared__ bool lastBlk;

    const int img = blockIdx.z;
    const int tid = threadIdx.x;
    const int lane = tid & 31, warp = tid >> 5;
    const int col = blockIdx.x * 256 + warp * 32 + lane;
    const int by = blockIdx.y * 32;
    const float* pimg = pred + (size_t)img * HH * WW;
    const float* timg = target + (size_t)img * HH * WW;
    uint8_t* bP8 = ((uint8_t*)g_binP) + (size_t)img * HH * WW;
    uint8_t* bT8 = ((uint8_t*)g_binT) + (size_t)img * HH * WW;
    const bool isL = (lane == 0) && (col > 0);
    const bool isR = (lane == 31) && (col < WW - 1);

    // rotation registers for d = sigmoid(p) - t (rows y-1, y, y+1)
    float d0, d1, p1v, t1v;
    {
        float p0v = 0.f, t0v = 0.f;
        if (by > 0) { p0v = sigm(pimg[(by - 1) * WW + col]); t0v = timg[(by - 1) * WW + col]; }
        d0 = p0v - t0v;
        p1v = sigm(pimg[by * WW + col]);
        t1v = timg[by * WW + col];
        d1 = p1v - t1v;
    }
    float dl0 = 0.f, dl1 = 0.f, dr0 = 0.f, dr1 = 0.f;
    if (isL) {
        float pp = 0.f, tt = 0.f;
        if (by > 0) { pp = sigm(pimg[(by - 1) * WW + col - 1]); tt = timg[(by - 1) * WW + col - 1]; }
        dl0 = pp - tt;
        dl1 = sigm(pimg[by * WW + col - 1]) - timg[by * WW + col - 1];
    }
    if (isR) {
        float pp = 0.f, tt = 0.f;
        if (by > 0) { pp = sigm(pimg[(by - 1) * WW + col + 1]); tt = timg[(by - 1) * WW + col + 1]; }
        dr0 = pp - tt;
        dr1 = sigm(pimg[by * WW + col + 1]) - timg[by * WW + col + 1];
    }

    float a0 = 0.f, a1 = 0.f, a2 = 0.f, a3 = 0.f, a4 = 0.f, a5 = 0.f;
#pragma unroll 4
    for (int y = by; y < by + 32; y++) {
        float p2v = 0.f, t2v = 0.f;
        if (y + 1 < HH) {
            float x = pimg[(y + 1) * WW + col];
            // sigmoid + both logs from one expf + one log1pf
            p2v = sigm(x);
            t2v = timg[(y + 1) * WW + col];
        }
        float d2 = p2v - t2v;
        float VcL = 0.f, VcR = 0.f;
        if (isL) {
            float pp = 0.f, tt = 0.f;
            if (y + 1 < HH) { pp = sigm(pimg[(y + 1) * WW + col - 1]); tt = timg[(y + 1) * WW + col - 1]; }
            float dl2 = pp - tt;
            VcL = dl0 + dl1 + dl2; dl0 = dl1; dl1 = dl2;
        }
        if (isR) {
            float pp = 0.f, tt = 0.f;
            if (y + 1 < HH) { pp = sigm(pimg[(y + 1) * WW + col + 1]); tt = timg[(y + 1) * WW + col + 1]; }
            float dr2 = pp - tt;
            VcR = dr0 + dr1 + dr2; dr0 = dr1; dr1 = dr2;
        }
        float Vc = d0 + d1 + d2;
        float Vl = __shfl_up_sync(0xFFFFFFFFu, Vc, 1);   if (lane == 0)  Vl = VcL;
        float Vr = __shfl_down_sync(0xFFFFFFFFu, Vc, 1); if (lane == 31) Vr = VcR;

        float p = p1v, t = t1v;
        uint8_t bp = (p > 0.5f) ? 1 : 0;
        uint8_t bt = (t > 0.5f) ? 1 : 0;
        size_t ridx = (size_t)y * WW + col;
        bP8[ridx] = bp;
        bT8[ridx] = bt;

        a0 += p; a1 += t; a2 += p * t;

        // focal (gamma=2, alpha=0.25): bce via clipped-log identities
        float pc = fminf(fmaxf(p, 1e-6f), 1.0f - 1e-6f);
        float bce = -(t * logf(pc) + (1.0f - t) * logf(1.0f - pc));
        float pt = (t == 1.0f) ? pc : (1.0f - pc);
        float fw = (1.0f - pt) * (1.0f - pt);
        float at = (t == 1.0f) ? 0.25f : 0.75f;
        a3 += at * fw * bce;

        float ds = Vl + Vc + Vr;
        float v = ds * (1.0f / 9.0f);
        if (bt) { a4 += v * v; a5 += 1.0f; }

        d0 = d1; d1 = d2; p1v = p2v; t1v = t2v;
    }

    // warp-shuffle reduction
    float vals[6] = {a0, a1, a2, a3, a4, a5};
#pragma unroll
    for (int q = 0; q < 6; q++) {
        float v = vals[q];
#pragma unroll
        for (int o = 16; o > 0; o >>= 1) v += __shfl_xor_sync(0xFFFFFFFFu, v, o);
        if (lane == 0) smw[warp * 6 + q] = v;
    }
    __syncthreads();
    int bid = (blockIdx.z * gridDim.y + blockIdx.y) * gridDim.x + blockIdx.x;
    if (tid < 6) {
        double s = 0.0;
        for (int w = 0; w < 8; w++) s += (double)smw[w * 6 + tid];
        g_partA[tid * NBLK_A + bid] = s;
    }
    __threadfence();
    __syncthreads();
    if (tid == 0) {
        unsigned int old = atomicInc(&g_cntA, NBLK_A - 1);
        lastBlk = (old == NBLK_A - 1);
    }
    __syncthreads();
    if (lastBlk) {   // fold the cross-block reduction in here
        for (int q = 0; q < 6; q++) {
            double s = 0.0;
            for (int i = tid; i < NBLK_A; i += 256) s += g_partA[q * NBLK_A + i];
            smd[tid] = s; __syncthreads();
            for (int st = 128; st > 0; st >>= 1) {
                if (tid < st) smd[tid] += smd[tid + st];
                __syncthreads();
            }
            if (tid == 0) g_sums[q] = smd[0];
            __syncthreads();
        }
    }
}

// ---------------- skeleton iteration: SWAR register sweep --------------------
// state closed over {0,1,2}: e = (sum3x3 >= 9); out = e ? (c==1 ? 2 : 1) : 0
__device__ __forceinline__ void iterArrive(int dst) {
    __threadfence();
    unsigned int old = atomicInc(&g_cntI, GRID_I - 1);
    if (old == GRID_I - 1) {   // last block: folded flag logic
        for (int w = 0; w < 2; w++) {
            if (!g_done[w]) {
                if (g_curr[w] == g_prev[w]) g_done[w] = 1;   // ints: |d|<1 <=> equal
                g_prev[w] = g_curr[w];
                g_last[w] = dst;
            }
            g_curr[w] = 0ULL;
        }
    }
}

__global__ __launch_bounds__(256) void iterKernel(int src, int dst) {
    __shared__ int smi[8];

    const int z = blockIdx.z;
    const int which = z >> 4;
    const int img = z & 15;
    const int tid = threadIdx.x;
    const int lane = tid & 31, warp = tid >> 5;

    if (g_done[which]) {
        if (tid == 0) iterArrive(dst);
        return;
    }

    const uint32_t* in32;
    uint32_t* out32;
    if (which == 0) {
        in32 = (src == 0) ? g_binP : ((src == 1) ? g_wp0 : g_wp1);
        out32 = (dst == 1) ? g_wp0 : g_wp1;
    } else {
        in32 = (src == 0) ? g_binT : ((src == 1) ? g_wt0 : g_wt1);
        out32 = (dst == 1) ? g_wt0 : g_wt1;
    }
    in32 += (size_t)img * (HH * WPR);
    out32 += (size_t)img * (HH * WPR);

    const int col = warp * 32 + lane;      // word column 0..255 (block = full width)
    const int by = blockIdx.y * 32;
    const bool isL = (lane == 0) && (col > 0);
    const bool isR = (lane == 31) && (col < WPR - 1);

    uint32_t r0 = (by > 0) ? in32[(by - 1) * WPR + col] : 0u;
    uint32_t r1 = in32[by * WPR + col];
    uint32_t l0 = 0, l1 = 0, q0 = 0, q1 = 0;
    if (isL) { l0 = (by > 0) ? in32[(by - 1) * WPR + col - 1] : 0u; l1 = in32[by * WPR + col - 1]; }
    if (isR) { q0 = (by > 0) ? in32[(by - 1) * WPR + col + 1] : 0u; q1 = in32[by * WPR + col + 1]; }

    int acc = 0;
#pragma unroll 8
    for (int y = by; y < by + 32; y++) {
        uint32_t r2 = (y + 1 < HH) ? in32[(y + 1) * WPR + col] : 0u;
        uint32_t VcL = 0u, VcR = 0u;
        if (isL) {
            uint32_t l2 = (y + 1 < HH) ? in32[(y + 1) * WPR + col - 1] : 0u;
            VcL = l0 + l1 + l2; l0 = l1; l1 = l2;
        }
        if (isR) {
            uint32_t q2 = (y + 1 < HH) ? in32[(y + 1) * WPR + col + 1] : 0u;
            VcR = q0 + q1 + q2; q0 = q1; q1 = q2;
        }
        uint32_t Vc = r0 + r1 + r2;
        uint32_t Vl = __shfl_up_sync(0xFFFFFFFFu, Vc, 1);   if (lane == 0)  Vl = VcL;
        uint32_t Vr = __shfl_down_sync(0xFFFFFFFFu, Vc, 1); if (lane == 31) Vr = VcR;

        uint32_t H = Vc + ((Vc >> 8) | (Vr << 24)) + ((Vc << 8) | (Vl >> 24));
        uint32_t c = r1;
        uint32_t ge = __vcmpgeu4(H, 0x09090909u);
        uint32_t eq1 = __vcmpeq4(c, 0x01010101u);
        uint32_t o = (ge & 0x01010101u) + (ge & eq1 & 0x01010101u);
        out32[y * WPR + col] = o;
        acc = __dp4a(o, 0x01010101u, (unsigned int)acc);

        r0 = r1; r1 = r2;
    }

#pragma unroll
    for (int o = 16; o > 0; o >>= 1) acc += __shfl_xor_sync(0xFFFFFFFFu, acc, o);
    if (lane == 0) smi[warp] = acc;
    __syncthreads();
    if (tid == 0) {
        int s = 0;
        for (int w = 0; w < 8; w++) s += smi[w];
        atomicAdd(&g_curr[which], (unsigned long long)s);
        iterArrive(dst);
    }
}

// ---------------- finalize: SWAR Sobel + skeleton dice (register sweep) ------
// Binary input => |gx|,|gy| <= 4; f = clip(skel + .5*sqrt(gx^2+gy^2+1e-8),0,1)
// quantizes: f = 1 if skel>=1 or g2>=4 else {0:5e-5, 1:.5, 2:.7071}[g2]
__global__ __launch_bounds__(256) void finKernel(float* __restrict__ out) {
    __shared__ float smw[24];
    __shared__ double smd[256];
    __shared__ double S3[3];
    __shared__ bool lastBlk;

    const int img = blockIdx.z;
    const int tid = threadIdx.x;
    const int lane = tid & 31, warp = tid >> 5;
    const int col = warp * 32 + lane;      // word column
    const int by = blockIdx.y * 16;

    const uint32_t* bP = g_binP + (size_t)img * (HH * WPR);
    const uint32_t* bT = g_binT + (size_t)img * (HH * WPR);
    const uint32_t* sp = ((g_last[0] == 1) ? g_wp0 : g_wp1) + (size_t)img * (HH * WPR);
    const uint32_t* st = ((g_last[1] == 1) ? g_wt0 : g_wt1) + (size_t)img * (HH * WPR);

    const bool isL = (lane == 0) && (col > 0);
    const bool isR = (lane == 31) && (col < WPR - 1);

    uint32_t p0 = (by > 0) ? bP[(by - 1) * WPR + col] : 0u;
    uint32_t p1 = bP[by * WPR + col];
    uint32_t t0 = (by > 0) ? bT[(by - 1) * WPR + col] : 0u;
    uint32_t t1 = bT[by * WPR + col];
    uint32_t lp0 = 0, lp1 = 0, lt0 = 0, lt1 = 0, rp0 = 0, rp1 = 0, rt0 = 0, rt1 = 0;
    if (isL) {
        lp0 = (by > 0) ? bP[(by - 1) * WPR + col - 1] : 0u; lp1 = bP[by * WPR + col - 1];
        lt0 = (by > 0) ? bT[(by - 1) * WPR + col - 1] : 0u; lt1 = bT[by * WPR + col - 1];
    }
    if (isR) {
        rp0 = (by > 0) ? bP[(by - 1) * WPR + col + 1] : 0u; rp1 = bP[by * WPR + col + 1];
        rt0 = (by > 0) ? bT[(by - 1) * WPR + col + 1] : 0u; rt1 = bT[by * WPR + col + 1];
    }

    float a0 = 0.f, a1 = 0.f, a2 = 0.f;
#pragma unroll 4
    for (int y = by; y < by + 16; y++) {
        uint32_t p2 = (y + 1 < HH) ? bP[(y + 1) * WPR + col] : 0u;
        uint32_t t2 = (y + 1 < HH) ? bT[(y + 1) * WPR + col] : 0u;
        uint32_t A_P = p0 + p1 + p1 + p2, B_P = p2 + (0x01010101u - p0);
        uint32_t A_T = t0 + t1 + t1 + t2, B_T = t2 + (0x01010101u - t0);

        // image-edge defaults: raw halo = 0 -> A = 0, B = bias
        uint32_t eAlP = 0u, eBlP = 0x01010101u, eAlT = 0u, eBlT = 0x01010101u;
        uint32_t eArP = 0u, eBrP = 0x01010101u, eArT = 0u, eBrT = 0x01010101u;
        if (isL) {
            uint32_t lp2 = (y + 1 < HH) ? bP[(y + 1) * WPR + col - 1] : 0u;
            uint32_t lt2 = (y + 1 < HH) ? bT[(y + 1) * WPR + col - 1] : 0u;
            eAlP = lp0 + lp1 + lp1 + lp2; eBlP = lp2 + (0x01010101u - lp0);
            eAlT = lt0 + lt1 + lt1 + lt2; eBlT = lt2 + (0x01010101u - lt0);
            lp0 = lp1; lp1 = lp2; lt0 = lt1; lt1 = lt2;
        }
        if (isR) {
            uint32_t rp2 = (y + 1 < HH) ? bP[(y + 1) * WPR + col + 1] : 0u;
            uint32_t rt2 = (y + 1 < HH) ? bT[(y + 1) * WPR + col + 1] : 0u;
            eArP = rp0 + rp1 + rp1 + rp2; eBrP = rp2 + (0x01010101u - rp0);
            eArT = rt0 + rt1 + rt1 + rt2; eBrT = rt2 + (0x01010101u - rt0);
            rp0 = rp1; rp1 = rp2; rt0 = rt1; rt1 = rt2;
        }

        uint32_t AlP = __shfl_up_sync(0xFFFFFFFFu, A_P, 1);   if (lane == 0)  AlP = eAlP;
        uint32_t ArP = __shfl_down_sync(0xFFFFFFFFu, A_P, 1); if (lane == 31) ArP = eArP;
        uint32_t BlP = __shfl_up_sync(0xFFFFFFFFu, B_P, 1);   if (lane == 0)  BlP = eBlP;
        uint32_t BrP = __shfl_down_sync(0xFFFFFFFFu, B_P, 1); if (lane == 31) BrP = eBrP;
        uint32_t AlT = __shfl_up_sync(0xFFFFFFFFu, A_T, 1);   if (lane == 0)  AlT = eAlT;
        uint32_t ArT = __shfl_down_sync(0xFFFFFFFFu, A_T, 1); if (lane == 31) ArT = eArT;
        uint32_t BlT = __shfl_up_sync(0xFFFFFFFFu, B_T, 1);   if (lane == 0)  BlT = eBlT;
        uint32_t BrT = __shfl_down_sync(0xFFFFFFFFu, B_T, 1); if (lane == 31) BrT = eBrT;

        // Hx bytes = gx + 4 in [0,8]; Hy bytes = gy + 4 in [0,8]
        uint32_t HxP = ((A_P >> 8) | (ArP << 24)) + (0x04040404u - ((A_P << 8) | (AlP >> 24)));
        uint32_t HyP = ((B_P << 8) | (BlP >> 24)) + B_P + B_P + ((B_P >> 8) | (BrP << 24));
        uint32_t HxT = ((A_T >> 8) | (ArT << 24)) + (0x04040404u - ((A_T << 8) | (AlT >> 24)));
        uint32_t HyT = ((B_T << 8) | (BlT >> 24)) + B_T + B_T + ((B_T >> 8) | (BrT << 24));

        uint32_t SP = sp[y * WPR + col];
        uint32_t ST = st[y * WPR + col];

#pragma unroll
        for (int b = 0; b < 4; b++) {
            int s = 8 * b;
            int gxp = (int)((HxP >> s) & 0xFF) - 4;
            int gyp = (int)((HyP >> s) & 0xFF) - 4;
            int g2p = gxp * gxp + gyp * gyp;
            int skp = (int)((SP >> s) & 0xFF);
            float fP = (skp | (g2p >= 4)) ? 1.0f
                     : (g2p == 0 ? 5.0e-5f : (g2p == 1 ? 0.5f : 0.70710678f));

            int gxt = (int)((HxT >> s) & 0xFF) - 4;
            int gyt = (int)((HyT >> s) & 0xFF) - 4;
            int g2t = gxt * gxt + gyt * gyt;
            int skt = (int)((ST >> s) & 0xFF);
            float fT = (skt | (g2t >= 4)) ? 1.0f
                     : (g2t == 0 ? 5.0e-5f : (g2t == 1 ? 0.5f : 0.70710678f));

            a0 += fP; a1 += fT; a2 += fP * fT;
        }
        p0 = p1; p1 = p2; t0 = t1; t1 = t2;
    }

    float vals[3] = {a0, a1, a2};
#pragma unroll
    for (int q = 0; q < 3; q++) {
        float v = vals[q];
#pragma unroll
        for (int o = 16; o > 0; o >>= 1) v += __shfl_xor_sync(0xFFFFFFFFu, v, o);
        if (lane == 0) smw[warp * 3 + q] = v;
    }
    __syncthreads();
    int bid = blockIdx.z * gridDim.y + blockIdx.y;
    if (tid < 3) {
        double sm = 0.0;
        for (int w = 0; w < 8; w++) sm += (double)smw[w * 3 + tid];
        g_partF[tid * NBLK_F + bid] = sm;
    }
    __threadfence();
    __syncthreads();
    if (tid == 0) {
        unsigned int old = atomicInc(&g_cntF, NBLK_F - 1);
        lastBlk = (old == NBLK_F - 1);
    }
    __syncthreads();
    if (lastBlk) {   // folded reduction + final scalar
        for (int q = 0; q < 3; q++) {
            double s = 0.0;
            for (int i = tid; i < NBLK_F; i += 256) s += g_partF[q * NBLK_F + i];
            smd[tid] = s; __syncthreads();
            for (int stp = 128; stp > 0; stp >>= 1) {
                if (tid < stp) smd[tid] += smd[tid + stp];
                __syncthreads();
            }
            if (tid == 0) S3[q] = smd[0];
            __syncthreads();
        }
        if (tid == 0) {
            double Sp = g_sums[0], St = g_sums[1], Spt = g_sums[2];
            double Sf = g_sums[3], Sc = g_sums[4], nw = g_sums[5];
            double S6 = S3[0], S7 = S3[1], S8 = S3[2];

            double skel_dice = (2.0 * S8 + 1.0) / (S6 + S7 + 1.0);
            double skeleton = 1.0 - skel_dice;
            double dice = 1.0 - (2.0 * Spt + 1.0) / (Sp + St + 1.0);
            double focal = Sf / (double)NPIX;
            focal = fmin(fmax(focal, 0.0), 10.0);
            double conn = (nw == 0.0) ? 0.0 : (Sc / fmax(nw, 1.0));

            double total = 0.3 * skeleton + 0.4 * dice + 0.2 * focal + 0.1 * conn;
            if (isnan(total) || isinf(total)) total = dice;
            out[0] = (float)total;
        }
    }
}

// ---------------- launch -----------------------------------------------------
extern "C" void kernel_launch(void* const* d_in, const int* in_sizes, int n_in,
                              void* d_out, int out_size) {
    const float* pred = (const float*)d_in[0];
    const float* target = (const float*)d_in[1];
    float* out = (float*)d_out;

    dim3 blk(256);
    dim3 grdA(4, 32, 16);    // 256-col x 32-row strips, batch
    dim3 grdI(1, 32, 32);    // full-width x 32-row strips; z: 0..15 P, 16..31 T
    dim3 grdF(1, 64, 16);    // full-width x 16-row strips, batch

    initKernel<<<1, 1>>>();
    mainKernel<<<grdA, blk>>>(pred, target);

    for (int i = 0; i < 10; i++) {
        int src = (i == 0) ? 0 : ((i % 2 == 0) ? 2 : 1);  // 0=bin, 1=w0, 2=w1
        int dst = (i % 2 == 0) ? 1 : 2;
        iterKernel<<<grdI, blk>>>(src, dst);
    }

    finKernel<<<grdF, blk>>>(out);
}

// round 5
// speedup vs baseline: 2.9453x; 1.4350x over previous
#include <cuda_runtime.h>
#include <math.h>
#include <stdint.h>

// Shapes fixed by the problem: [16, 1, 1024, 1024] float32
#define BB 16
#define HH 1024
#define WW 1024
#define WPR 256                       // uint32 words per row (1024/4)
#define WPR4 64                       // uint4 per row
#define NPIX (BB * HH * WW)           // 16777216
#define NWORD (NPIX / 4)
#define NBLK_A 2048                   // main grid blocks (4*32*16)
#define NBLK_F 1024                   // fin grid blocks (64*16)
#define GRID_I 256                    // iter grid blocks (8 strips * 32 z)

// ---------------- device scratch (no runtime allocation) ---------------------
__device__ uint32_t g_binP[NWORD];    // binary(pred_prob), 1 byte/pixel
__device__ uint32_t g_binT[NWORD];    // binary(target)
__device__ uint32_t g_wp0[NWORD];     // skeleton ping-pong (pred)
__device__ uint32_t g_wp1[NWORD];
__device__ uint32_t g_wt0[NWORD];     // skeleton ping-pong (target)
__device__ uint32_t g_wt1[NWORD];

__device__ double g_partA[6 * NBLK_A];
__device__ double g_partF[3 * NBLK_F];

__device__ unsigned long long g_curr[2];
__device__ unsigned long long g_prev[2];
__device__ int g_done[2];
__device__ int g_last[2];             // 1 -> wX0, 2 -> wX1 holds final skeleton
__device__ unsigned int g_cntA;
__device__ unsigned int g_cntF;
__device__ unsigned int g_cntI;       // iter arrival counter (self-reset via wrap)
__device__ double g_sums[6];          // Sp,St,Spt,Sfocal,Sconn,nwater

// ---------------- init -------------------------------------------------------
__global__ void initKernel() {
    g_curr[0] = g_curr[1] = 0ULL;
    g_prev[0] = g_prev[1] = 0xFFFFFFFFFFFFFFFFULL;  // "inf" sentinel
    g_done[0] = g_done[1] = 0;
    g_last[0] = g_last[1] = 1;
    g_cntA = 0; g_cntF = 0; g_cntI = 0;
}

__device__ __forceinline__ float sigm_fast(float x) {
    return __fdividef(1.0f, 1.0f + __expf(-x));
}

// ---------------- pass 1: fused elementwise + connectivity (register sweep) --
// t is exactly 0.0 or 1.0. With p = sigmoid(x), L = log(p):
//   log(1-p) = L - x, so bce(t=0) = clamp(x - L, ~1e-6, 13.8155106)
//   bce(t=1) = clamp(-L, ~1e-6, 13.8155106)        (== clipping p to [1e-6, 1-1e-6])
__global__ __launch_bounds__(256) void mainKernel(const float* __restrict__ pred,
                                                  const float* __restrict__ target) {
    __shared__ float smw[48];
    __shared__ double smd[256];
    __shared__ bool lastBlk;

    const int img = blockIdx.z;
    const int tid = threadIdx.x;
    const int lane = tid & 31, warp = tid >> 5;
    const int col = blockIdx.x * 256 + warp * 32 + lane;
    const int by = blockIdx.y * 32;
    const float* pimg = pred + (size_t)img * HH * WW;
    const float* timg = target + (size_t)img * HH * WW;
    uint8_t* bP8 = ((uint8_t*)g_binP) + (size_t)img * HH * WW;
    uint8_t* bT8 = ((uint8_t*)g_binT) + (size_t)img * HH * WW;
    const bool isL = (lane == 0) && (col > 0);
    const bool isR = (lane == 31) && (col < WW - 1);

    // rotation registers (rows y-1, y, y+1): d = p - t, plus x, p, L, t at row y
    float d0, d1, p1v, t1v, x1v, L1v;
    {
        float p0v = 0.f, t0v = 0.f;
        if (by > 0) { p0v = sigm_fast(pimg[(by - 1) * WW + col]); t0v = timg[(by - 1) * WW + col]; }
        d0 = p0v - t0v;
        x1v = pimg[by * WW + col];
        p1v = sigm_fast(x1v);
        L1v = __logf(p1v);
        t1v = timg[by * WW + col];
        d1 = p1v - t1v;
    }
    float dl0 = 0.f, dl1 = 0.f, dr0 = 0.f, dr1 = 0.f;
    if (isL) {
        float pp = 0.f, tt = 0.f;
        if (by > 0) { pp = sigm_fast(pimg[(by - 1) * WW + col - 1]); tt = timg[(by - 1) * WW + col - 1]; }
        dl0 = pp - tt;
        dl1 = sigm_fast(pimg[by * WW + col - 1]) - timg[by * WW + col - 1];
    }
    if (isR) {
        float pp = 0.f, tt = 0.f;
        if (by > 0) { pp = sigm_fast(pimg[(by - 1) * WW + col + 1]); tt = timg[(by - 1) * WW + col + 1]; }
        dr0 = pp - tt;
        dr1 = sigm_fast(pimg[by * WW + col + 1]) - timg[by * WW + col + 1];
    }

    float a0 = 0.f, a1 = 0.f, a2 = 0.f, a3 = 0.f, a4 = 0.f, a5 = 0.f;
#pragma unroll 4
    for (int y = by; y < by + 32; y++) {
        float p2v = 0.f, t2v = 0.f, x2v = 0.f, L2v = 0.f;
        if (y + 1 < HH) {
            x2v = pimg[(y + 1) * WW + col];
            p2v = sigm_fast(x2v);
            L2v = __logf(p2v);
            t2v = timg[(y + 1) * WW + col];
        }
        float d2 = p2v - t2v;
        float VcL = 0.f, VcR = 0.f;
        if (isL) {
            float pp = 0.f, tt = 0.f;
            if (y + 1 < HH) { pp = sigm_fast(pimg[(y + 1) * WW + col - 1]); tt = timg[(y + 1) * WW + col - 1]; }
            float dl2 = pp - tt;
            VcL = dl0 + dl1 + dl2; dl0 = dl1; dl1 = dl2;
        }
        if (isR) {
            float pp = 0.f, tt = 0.f;
            if (y + 1 < HH) { pp = sigm_fast(pimg[(y + 1) * WW + col + 1]); tt = timg[(y + 1) * WW + col + 1]; }
            float dr2 = pp - tt;
            VcR = dr0 + dr1 + dr2; dr0 = dr1; dr1 = dr2;
        }
        float Vc = d0 + d1 + d2;
        float Vl = __shfl_up_sync(0xFFFFFFFFu, Vc, 1);   if (lane == 0)  Vl = VcL;
        float Vr = __shfl_down_sync(0xFFFFFFFFu, Vc, 1); if (lane == 31) Vr = VcR;

        float p = p1v, t = t1v;
        uint8_t bp = (p > 0.5f) ? 1 : 0;
        uint8_t bt = (t > 0.5f) ? 1 : 0;
        size_t ridx = (size_t)y * WW + col;
        bP8[ridx] = bp;
        bT8[ridx] = bt;

        a0 += p; a1 += t; a2 += p * t;

        // focal (gamma=2, alpha=0.25), t in {0,1} exact
        float pcl = fminf(fmaxf(p, 1e-6f), 1.0f - 1e-6f);
        float omp = 1.0f - pcl;
        bool one = (t == 1.0f);
        float bce = one ? (-L1v) : (x1v - L1v);
        bce = fminf(fmaxf(bce, 1.0000005e-6f), 13.8155106f);
        float fw = one ? (omp * omp) : (pcl * pcl);
        float at = one ? 0.25f : 0.75f;
        a3 += at * fw * bce;

        float ds = Vl + Vc + Vr;
        float v = ds * (1.0f / 9.0f);
        if (bt) { a4 += v * v; a5 += 1.0f; }

        d0 = d1; d1 = d2; p1v = p2v; t1v = t2v; x1v = x2v; L1v = L2v;
    }

    // warp-shuffle reduction
    float vals[6] = {a0, a1, a2, a3, a4, a5};
#pragma unroll
    for (int q = 0; q < 6; q++) {
        float v = vals[q];
#pragma unroll
        for (int o = 16; o > 0; o >>= 1) v += __shfl_xor_sync(0xFFFFFFFFu, v, o);
        if (lane == 0) smw[warp * 6 + q] = v;
    }
    __syncthreads();
    int bid = (blockIdx.z * gridDim.y + blockIdx.y) * gridDim.x + blockIdx.x;
    if (tid < 6) {
        double s = 0.0;
        for (int w = 0; w < 8; w++) s += (double)smw[w * 6 + tid];
        g_partA[tid * NBLK_A + bid] = s;
    }
    __threadfence();
    __syncthreads();
    if (tid == 0) {
        unsigned int old = atomicInc(&g_cntA, NBLK_A - 1);
        lastBlk = (old == NBLK_A - 1);
    }
    __syncthreads();
    if (lastBlk) {
        for (int q = 0; q < 6; q++) {
            double s = 0.0;
            for (int i = tid; i < NBLK_A; i += 256) s += g_partA[q * NBLK_A + i];
            smd[tid] = s; __syncthreads();
            for (int st = 128; st > 0; st >>= 1) {
                if (tid < st) smd[tid] += smd[tid + st];
                __syncthreads();
            }
            if (tid == 0) g_sums[q] = smd[0];
            __syncthreads();
        }
    }
}

// ---------------- skeleton iteration: uint4 SWAR, 16 px/thread/row ----------
// state closed over {0,1,2}: e = (sum3x3 >= 9); out = e ? (c==1 ? 2 : 1) : 0
__device__ __forceinline__ void iterArrive(int dst) {
    __threadfence();
    unsigned int old = atomicInc(&g_cntI, GRID_I - 1);
    if (old == GRID_I - 1) {   // last block: folded flag logic
        for (int w = 0; w < 2; w++) {
            if (!g_done[w]) {
                if (g_curr[w] == g_prev[w]) g_done[w] = 1;   // ints: |d|<1 <=> equal
                g_prev[w] = g_curr[w];
                g_last[w] = dst;
            }
            g_curr[w] = 0ULL;
        }
    }
}

__global__ __launch_bounds__(256) void iterKernel(int src, int dst) {
    __shared__ int smi[8];

    const int tid = threadIdx.x;
    const int z = blockIdx.z;            // 0..31: 0..15 P, 16..31 T
    const int strip = blockIdx.x;        // rows [strip*128, +128)
    const int which = z >> 4;
    const int img = z & 15;

    if (g_done[which]) {                 // frozen plane: just participate in arrival
        if (tid == 0) iterArrive(dst);
        return;
    }

    const int g = tid >> 6;              // 0..3 row-groups of 32
    const int j = tid & 63;              // uint4 column 0..63
    const int lane = tid & 31;
    const int rowBase = strip * 128 + g * 32;
    const bool needL = (lane == 0) && (j > 0);
    const bool needR = (lane == 31) && (j < WPR4 - 1);

    const uint32_t* inw;
    uint32_t* outw;
    if (which == 0) {
        inw = (src == 0) ? g_binP : ((src == 1) ? g_wp0 : g_wp1);
        outw = (dst == 1) ? g_wp0 : g_wp1;
    } else {
        inw = (src == 0) ? g_binT : ((src == 1) ? g_wt0 : g_wt1);
        outw = (dst == 1) ? g_wt0 : g_wt1;
    }
    inw += (size_t)img * (HH * WPR);
    outw += (size_t)img * (HH * WPR);
    const uint4* in4 = (const uint4*)inw;
    uint4* out4 = (uint4*)outw;

    uint4 r0 = make_uint4(0u, 0u, 0u, 0u);
    if (rowBase > 0) r0 = in4[(rowBase - 1) * WPR4 + j];
    uint4 r1 = in4[rowBase * WPR4 + j];
    uint32_t l0 = 0, l1 = 0, q0 = 0, q1 = 0;
    if (needL) {
        if (rowBase > 0) l0 = inw[(rowBase - 1) * WPR + 4 * j - 1];
        l1 = inw[rowBase * WPR + 4 * j - 1];
    }
    if (needR) {
        if (rowBase > 0) q0 = inw[(rowBase - 1) * WPR + 4 * j + 4];
        q1 = inw[rowBase * WPR + 4 * j + 4];
    }

    int acc = 0;
#pragma unroll 4
    for (int y = rowBase; y < rowBase + 32; y++) {
        uint4 r2 = make_uint4(0u, 0u, 0u, 0u);
        if (y + 1 < HH) r2 = in4[(y + 1) * WPR4 + j];
        uint32_t l2 = 0, q2 = 0;
        if (needL && (y + 1 < HH)) l2 = inw[(y + 1) * WPR + 4 * j - 1];
        if (needR && (y + 1 < HH)) q2 = inw[(y + 1) * WPR + 4 * j + 4];

        uint32_t Vx = r0.x + r1.x + r2.x;
        uint32_t Vy = r0.y + r1.y + r2.y;
        uint32_t Vz = r0.z + r1.z + r2.z;
        uint32_t Vw = r0.w + r1.w + r2.w;
        uint32_t VL = __shfl_up_sync(0xFFFFFFFFu, Vw, 1);
        if (lane == 0) VL = l0 + l1 + l2;
        uint32_t VR = __shfl_down_sync(0xFFFFFFFFu, Vx, 1);
        if (lane == 31) VR = q0 + q1 + q2;

        uint32_t Hx = Vx + ((Vx >> 8) | (Vy << 24)) + ((Vx << 8) | (VL >> 24));
        uint32_t Hy = Vy + ((Vy >> 8) | (Vz << 24)) + ((Vy << 8) | (Vx >> 24));
        uint32_t Hz = Vz + ((Vz >> 8) | (Vw << 24)) + ((Vz << 8) | (Vy >> 24));
        uint32_t Hw = Vw + ((Vw >> 8) | (VR << 24)) + ((Vw << 8) | (Vz >> 24));

        uint4 o;
        uint32_t ge;
        ge = __vcmpgeu4(Hx, 0x09090909u);
        o.x = (ge & 0x01010101u) + (ge & __vcmpeq4(r1.x, 0x01010101u) & 0x01010101u);
        ge = __vcmpgeu4(Hy, 0x09090909u);
        o.y = (ge & 0x01010101u) + (ge & __vcmpeq4(r1.y, 0x01010101u) & 0x01010101u);
        ge = __vcmpgeu4(Hz, 0x09090909u);
        o.z = (ge & 0x01010101u) + (ge & __vcmpeq4(r1.z, 0x01010101u) & 0x01010101u);
        ge = __vcmpgeu4(Hw, 0x09090909u);
        o.w = (ge & 0x01010101u) + (ge & __vcmpeq4(r1.w, 0x01010101u) & 0x01010101u);

        out4[y * WPR4 + j] = o;
        acc = __dp4a(o.x, 0x01010101u, (unsigned int)acc);
        acc = __dp4a(o.y, 0x01010101u, (unsigned int)acc);
        acc = __dp4a(o.z, 0x01010101u, (unsigned int)acc);
        acc = __dp4a(o.w, 0x01010101u, (unsigned int)acc);

        r0 = r1; r1 = r2;
        l0 = l1; l1 = l2; q0 = q1; q1 = q2;
    }

#pragma unroll
    for (int o = 16; o > 0; o >>= 1) acc += __shfl_xor_sync(0xFFFFFFFFu, acc, o);
    if (lane == 0) smi[tid >> 5] = acc;
    __syncthreads();
    if (tid == 0) {
        int s = 0;
        for (int w = 0; w < 8; w++) s += smi[w];
        atomicAdd(&g_curr[which], (unsigned long long)s);
        iterArrive(dst);
    }
}

// ---------------- finalize: SWAR Sobel + skeleton dice (register sweep) ------
// Binary input => |gx|,|gy| <= 4; f = clip(skel + .5*sqrt(gx^2+gy^2+1e-8),0,1)
// quantizes: f = 1 if skel>=1 or g2>=4 else {0:5e-5, 1:.5, 2:.7071}[g2]
__global__ __launch_bounds__(256) void finKernel(float* __restrict__ out) {
    __shared__ float smw[24];
    __shared__ double smd[256];
    __shared__ double S3[3];
    __shared__ bool lastBlk;

    const int img = blockIdx.z;
    const int tid = threadIdx.x;
    const int lane = tid & 31, warp = tid >> 5;
    const int col = warp * 32 + lane;
    const int by = blockIdx.y * 16;

    const uint32_t* bP = g_binP + (size_t)img * (HH * WPR);
    const uint32_t* bT = g_binT + (size_t)img * (HH * WPR);
    const uint32_t* sp = ((g_last[0] == 1) ? g_wp0 : g_wp1) + (size_t)img * (HH * WPR);
    const uint32_t* st = ((g_last[1] == 1) ? g_wt0 : g_wt1) + (size_t)img * (HH * WPR);

    const bool isL = (lane == 0) && (col > 0);
    const bool isR = (lane == 31) && (col < WPR - 1);

    uint32_t p0 = (by > 0) ? bP[(by - 1) * WPR + col] : 0u;
    uint32_t p1 = bP[by * WPR + col];
    uint32_t t0 = (by > 0) ? bT[(by - 1) * WPR + col] : 0u;
    uint32_t t1 = bT[by * WPR + col];
    uint32_t lp0 = 0, lp1 = 0, lt0 = 0, lt1 = 0, rp0 = 0, rp1 = 0, rt0 = 0, rt1 = 0;
    if (isL) {
        lp0 = (by > 0) ? bP[(by - 1) * WPR + col - 1] : 0u; lp1 = bP[by * WPR + col - 1];
        lt0 = (by > 0) ? bT[(by - 1) * WPR + col - 1] : 0u; lt1 = bT[by * WPR + col - 1];
    }
    if (isR) {
        rp0 = (by > 0) ? bP[(by - 1) * WPR + col + 1] : 0u; rp1 = bP[by * WPR + col + 1];
        rt0 = (by > 0) ? bT[(by - 1) * WPR + col + 1] : 0u; rt1 = bT[by * WPR + col + 1];
    }

    float a0 = 0.f, a1 = 0.f, a2 = 0.f;
#pragma unroll 4
    for (int y = by; y < by + 16; y++) {
        uint32_t p2 = (y + 1 < HH) ? bP[(y + 1) * WPR + col] : 0u;
        uint32_t t2 = (y + 1 < HH) ? bT[(y + 1) * WPR + col] : 0u;
        uint32_t A_P = p0 + p1 + p1 + p2, B_P = p2 + (0x01010101u - p0);
        uint32_t A_T = t0 + t1 + t1 + t2, B_T = t2 + (0x01010101u - t0);

        uint32_t eAlP = 0u, eBlP = 0x01010101u, eAlT = 0u, eBlT = 0x01010101u;
        uint32_t eArP = 0u, eBrP = 0x01010101u, eArT = 0u, eBrT = 0x01010101u;
        if (isL) {
            uint32_t lp2 = (y + 1 < HH) ? bP[(y + 1) * WPR + col - 1] : 0u;
            uint32_t lt2 = (y + 1 < HH) ? bT[(y + 1) * WPR + col - 1] : 0u;
            eAlP = lp0 + lp1 + lp1 + lp2; eBlP = lp2 + (0x01010101u - lp0);
            eAlT = lt0 + lt1 + lt1 + lt2; eBlT = lt2 + (0x01010101u - lt0);
            lp0 = lp1; lp1 = lp2; lt0 = lt1; lt1 = lt2;
        }
        if (isR) {
            uint32_t rp2 = (y + 1 < HH) ? bP[(y + 1) * WPR + col + 1] : 0u;
            uint32_t rt2 = (y + 1 < HH) ? bT[(y + 1) * WPR + col + 1] : 0u;
            eArP = rp0 + rp1 + rp1 + rp2; eBrP = rp2 + (0x01010101u - rp0);
            eArT = rt0 + rt1 + rt1 + rt2; eBrT = rt2 + (0x01010101u - rt0);
            rp0 = rp1; rp1 = rp2; rt0 = rt1; rt1 = rt2;
        }

        uint32_t AlP = __shfl_up_sync(0xFFFFFFFFu, A_P, 1);   if (lane == 0)  AlP = eAlP;
        uint32_t ArP = __shfl_down_sync(0xFFFFFFFFu, A_P, 1); if (lane == 31) ArP = eArP;
        uint32_t BlP = __shfl_up_sync(0xFFFFFFFFu, B_P, 1);   if (lane == 0)  BlP = eBlP;
        uint32_t BrP = __shfl_down_sync(0xFFFFFFFFu, B_P, 1); if (lane == 31) BrP = eBrP;
        uint32_t AlT = __shfl_up_sync(0xFFFFFFFFu, A_T, 1);   if (lane == 0)  AlT = eAlT;
        uint32_t ArT = __shfl_down_sync(0xFFFFFFFFu, A_T, 1); if (lane == 31) ArT = eArT;
        uint32_t BlT = __shfl_up_sync(0xFFFFFFFFu, B_T, 1);   if (lane == 0)  BlT = eBlT;
        uint32_t BrT = __shfl_down_sync(0xFFFFFFFFu, B_T, 1); if (lane == 31) BrT = eBrT;

        uint32_t HxP = ((A_P >> 8) | (ArP << 24)) + (0x04040404u - ((A_P << 8) | (AlP >> 24)));
        uint32_t HyP = ((B_P << 8) | (BlP >> 24)) + B_P + B_P + ((B_P >> 8) | (BrP << 24));
        uint32_t HxT = ((A_T >> 8) | (ArT << 24)) + (0x04040404u - ((A_T << 8) | (AlT >> 24)));
        uint32_t HyT = ((B_T << 8) | (BlT >> 24)) + B_T + B_T + ((B_T >> 8) | (BrT << 24));

        uint32_t SP = sp[y * WPR + col];
        uint32_t ST = st[y * WPR + col];

#pragma unroll
        for (int b = 0; b < 4; b++) {
            int s = 8 * b;
            int gxp = (int)((HxP >> s) & 0xFF) - 4;
            int gyp = (int)((HyP >> s) & 0xFF) - 4;
            int g2p = gxp * gxp + gyp * gyp;
            int skp = (int)((SP >> s) & 0xFF);
            float fP = (skp | (g2p >= 4)) ? 1.0f
                     : (g2p == 0 ? 5.0e-5f : (g2p == 1 ? 0.5f : 0.70710678f));

            int gxt = (int)((HxT >> s) & 0xFF) - 4;
            int gyt = (int)((HyT >> s) & 0xFF) - 4;
            int g2t = gxt * gxt + gyt * gyt;
            int skt = (int)((ST >> s) & 0xFF);
            float fT = (skt | (g2t >= 4)) ? 1.0f
                     : (g2t == 0 ? 5.0e-5f : (g2t == 1 ? 0.5f : 0.70710678f));

            a0 += fP; a1 += fT; a2 += fP * fT;
        }
        p0 = p1; p1 = p2; t0 = t1; t1 = t2;
    }

    float vals[3] = {a0, a1, a2};
#pragma unroll
    for (int q = 0; q < 3; q++) {
        float v = vals[q];
#pragma unroll
        for (int o = 16; o > 0; o >>= 1) v += __shfl_xor_sync(0xFFFFFFFFu, v, o);
        if (lane == 0) smw[warp * 3 + q] = v;
    }
    __syncthreads();
    int bid = blockIdx.z * gridDim.y + blockIdx.y;
    if (tid < 3) {
        double sm = 0.0;
        for (int w = 0; w < 8; w++) sm += (double)smw[w * 3 + tid];
        g_partF[tid * NBLK_F + bid] = sm;
    }
    __threadfence();
    __syncthreads();
    if (tid == 0) {
        unsigned int old = atomicInc(&g_cntF, NBLK_F - 1);
        lastBlk = (old == NBLK_F - 1);
    }
    __syncthreads();
    if (lastBlk) {
        for (int q = 0; q < 3; q++) {
            double s = 0.0;
            for (int i = tid; i < NBLK_F; i += 256) s += g_partF[q * NBLK_F + i];
            smd[tid] = s; __syncthreads();
            for (int stp = 128; stp > 0; stp >>= 1) {
                if (tid < stp) smd[tid] += smd[tid + stp];
                __syncthreads();
            }
            if (tid == 0) S3[q] = smd[0];
            __syncthreads();
        }
        if (tid == 0) {
            double Sp = g_sums[0], St = g_sums[1], Spt = g_sums[2];
            double Sf = g_sums[3], Sc = g_sums[4], nw = g_sums[5];
            double S6 = S3[0], S7 = S3[1], S8 = S3[2];

            double skel_dice = (2.0 * S8 + 1.0) / (S6 + S7 + 1.0);
            double skeleton = 1.0 - skel_dice;
            double dice = 1.0 - (2.0 * Spt + 1.0) / (Sp + St + 1.0);
            double focal = Sf / (double)NPIX;
            focal = fmin(fmax(focal, 0.0), 10.0);
            double conn = (nw == 0.0) ? 0.0 : (Sc / fmax(nw, 1.0));

            double total = 0.3 * skeleton + 0.4 * dice + 0.2 * focal + 0.1 * conn;
            if (isnan(total) || isinf(total)) total = dice;
            out[0] = (float)total;
        }
    }
}

// ---------------- launch -----------------------------------------------------
extern "C" void kernel_launch(void* const* d_in, const int* in_sizes, int n_in,
                              void* d_out, int out_size) {
    const float* pred = (const float*)d_in[0];
    const float* target = (const float*)d_in[1];
    float* out = (float*)d_out;

    dim3 blk(256);
    dim3 grdA(4, 32, 16);    // 256-col x 32-row strips, batch
    dim3 grdI(8, 1, 32);     // 8 row-strips of 128; z: 0..15 P, 16..31 T
    dim3 grdF(1, 64, 16);    // full-width x 16-row strips, batch

    initKernel<<<1, 1>>>();
    mainKernel<<<grdA, blk>>>(pred, target);

    for (int i = 0; i < 10; i++) {
        int src = (i == 0) ? 0 : ((i % 2 == 0) ? 2 : 1);  // 0=bin, 1=w0, 2=w1
        int dst = (i % 2 == 0) ? 1 : 2;
        iterKernel<<<grdI, blk>>>(src, dst);
    }

    finKernel<<<grdF, blk>>>(out);
}

// round 6
// speedup vs baseline: 3.1601x; 1.0729x over previous
#include <cuda_runtime.h>
#include <math.h>
#include <stdint.h>

// Shapes fixed by the problem: [16, 1, 1024, 1024] float32
#define BB 16
#define HH 1024
#define WW 1024
#define WPR 256                       // uint32 words per row (1024/4)
#define WPR4 64                       // uint4 per row
#define NPIX (BB * HH * WW)           // 16777216
#define NWORD (NPIX / 4)
#define NBLK_A 2048                   // main grid blocks (4*32*16)
#define NBLK_F 1024                   // fin grid blocks (64*16)
#define GRID_I 1024                   // iter grid blocks (32 strips * 32 z)

// ---------------- device scratch (no runtime allocation) ---------------------
__device__ uint32_t g_binP[NWORD];    // binary(pred_prob), 1 byte/pixel
__device__ uint32_t g_binT[NWORD];    // binary(target)
__device__ uint32_t g_wp0[NWORD];     // skeleton ping-pong (pred)
__device__ uint32_t g_wp1[NWORD];
__device__ uint32_t g_wt0[NWORD];     // skeleton ping-pong (target)
__device__ uint32_t g_wt1[NWORD];

__device__ double g_partA[6 * NBLK_A];
__device__ double g_partF[3 * NBLK_F];

__device__ unsigned long long g_curr[2];
__device__ unsigned long long g_prev[2];
__device__ int g_done[2];
__device__ int g_last[2];             // 1 -> wX0, 2 -> wX1 holds final skeleton
__device__ unsigned int g_cntA;
__device__ unsigned int g_cntF;
__device__ unsigned int g_cntI;       // iter arrival counter (self-reset via wrap)
__device__ double g_sums[6];          // Sp,St,Spt,Sfocal,Sconn,nwater

// ---------------- init -------------------------------------------------------
__global__ void initKernel() {
    g_curr[0] = g_curr[1] = 0ULL;
    g_prev[0] = g_prev[1] = 0xFFFFFFFFFFFFFFFFULL;  // "inf" sentinel
    g_done[0] = g_done[1] = 0;
    g_last[0] = g_last[1] = 1;
    g_cntA = 0; g_cntF = 0; g_cntI = 0;
}

__device__ __forceinline__ float sigm_fast(float x) {
    return __fdividef(1.0f, 1.0f + __expf(-x));
}

// ---------------- pass 1: fused elementwise + connectivity (register sweep) --
// t is exactly 0.0 or 1.0. With p = sigmoid(x), L = log(p):
//   log(1-p) = L - x, so bce(t=0) = clamp(x - L, ~1e-6, 13.8155106)
//   bce(t=1) = clamp(-L, ~1e-6, 13.8155106)        (== clipping p to [1e-6, 1-1e-6])
__global__ __launch_bounds__(256) void mainKernel(const float* __restrict__ pred,
                                                  const float* __restrict__ target) {
    __shared__ float smw[48];
    __shared__ double smd[256];
    __shared__ bool lastBlk;

    const int img = blockIdx.z;
    const int tid = threadIdx.x;
    const int lane = tid & 31, warp = tid >> 5;
    const int col = blockIdx.x * 256 + warp * 32 + lane;
    const int by = blockIdx.y * 32;
    const float* pimg = pred + (size_t)img * HH * WW;
    const float* timg = target + (size_t)img * HH * WW;
    uint8_t* bP8 = ((uint8_t*)g_binP) + (size_t)img * HH * WW;
    uint8_t* bT8 = ((uint8_t*)g_binT) + (size_t)img * HH * WW;
    const bool isL = (lane == 0) && (col > 0);
    const bool isR = (lane == 31) && (col < WW - 1);

    // rotation registers (rows y-1, y, y+1): d = p - t, plus x, p, L, t at row y
    float d0, d1, p1v, t1v, x1v, L1v;
    {
        float p0v = 0.f, t0v = 0.f;
        if (by > 0) { p0v = sigm_fast(pimg[(by - 1) * WW + col]); t0v = timg[(by - 1) * WW + col]; }
        d0 = p0v - t0v;
        x1v = pimg[by * WW + col];
        p1v = sigm_fast(x1v);
        L1v = __logf(p1v);
        t1v = timg[by * WW + col];
        d1 = p1v - t1v;
    }
    float dl0 = 0.f, dl1 = 0.f, dr0 = 0.f, dr1 = 0.f;
    if (isL) {
        float pp = 0.f, tt = 0.f;
        if (by > 0) { pp = sigm_fast(pimg[(by - 1) * WW + col - 1]); tt = timg[(by - 1) * WW + col - 1]; }
        dl0 = pp - tt;
        dl1 = sigm_fast(pimg[by * WW + col - 1]) - timg[by * WW + col - 1];
    }
    if (isR) {
        float pp = 0.f, tt = 0.f;
        if (by > 0) { pp = sigm_fast(pimg[(by - 1) * WW + col + 1]); tt = timg[(by - 1) * WW + col + 1]; }
        dr0 = pp - tt;
        dr1 = sigm_fast(pimg[by * WW + col + 1]) - timg[by * WW + col + 1];
    }

    float a0 = 0.f, a1 = 0.f, a2 = 0.f, a3 = 0.f, a4 = 0.f, a5 = 0.f;
#pragma unroll 4
    for (int y = by; y < by + 32; y++) {
        float p2v = 0.f, t2v = 0.f, x2v = 0.f, L2v = 0.f;
        if (y + 1 < HH) {
            x2v = pimg[(y + 1) * WW + col];
            p2v = sigm_fast(x2v);
            L2v = __logf(p2v);
            t2v = timg[(y + 1) * WW + col];
        }
        float d2 = p2v - t2v;
        float VcL = 0.f, VcR = 0.f;
        if (isL) {
            float pp = 0.f, tt = 0.f;
            if (y + 1 < HH) { pp = sigm_fast(pimg[(y + 1) * WW + col - 1]); tt = timg[(y + 1) * WW + col - 1]; }
            float dl2 = pp - tt;
            VcL = dl0 + dl1 + dl2; dl0 = dl1; dl1 = dl2;
        }
        if (isR) {
            float pp = 0.f, tt = 0.f;
            if (y + 1 < HH) { pp = sigm_fast(pimg[(y + 1) * WW + col + 1]); tt = timg[(y + 1) * WW + col + 1]; }
            float dr2 = pp - tt;
            VcR = dr0 + dr1 + dr2; dr0 = dr1; dr1 = dr2;
        }
        float Vc = d0 + d1 + d2;
        float Vl = __shfl_up_sync(0xFFFFFFFFu, Vc, 1);   if (lane == 0)  Vl = VcL;
        float Vr = __shfl_down_sync(0xFFFFFFFFu, Vc, 1); if (lane == 31) Vr = VcR;

        float p = p1v, t = t1v;
        uint8_t bp = (p > 0.5f) ? 1 : 0;
        uint8_t bt = (t > 0.5f) ? 1 : 0;
        size_t ridx = (size_t)y * WW + col;
        bP8[ridx] = bp;
        bT8[ridx] = bt;

        a0 += p; a1 += t; a2 += p * t;

        // focal (gamma=2, alpha=0.25), t in {0,1} exact
        float pcl = fminf(fmaxf(p, 1e-6f), 1.0f - 1e-6f);
        float omp = 1.0f - pcl;
        bool one = (t == 1.0f);
        float bce = one ? (-L1v) : (x1v - L1v);
        bce = fminf(fmaxf(bce, 1.0000005e-6f), 13.8155106f);
        float fw = one ? (omp * omp) : (pcl * pcl);
        float at = one ? 0.25f : 0.75f;
        a3 += at * fw * bce;

        float ds = Vl + Vc + Vr;
        float v = ds * (1.0f / 9.0f);
        if (bt) { a4 += v * v; a5 += 1.0f; }

        d0 = d1; d1 = d2; p1v = p2v; t1v = t2v; x1v = x2v; L1v = L2v;
    }

    // warp-shuffle reduction
    float vals[6] = {a0, a1, a2, a3, a4, a5};
#pragma unroll
    for (int q = 0; q < 6; q++) {
        float v = vals[q];
#pragma unroll
        for (int o = 16; o > 0; o >>= 1) v += __shfl_xor_sync(0xFFFFFFFFu, v, o);
        if (lane == 0) smw[warp * 6 + q] = v;
    }
    __syncthreads();
    int bid = (blockIdx.z * gridDim.y + blockIdx.y) * gridDim.x + blockIdx.x;
    if (tid < 6) {
        double s = 0.0;
        for (int w = 0; w < 8; w++) s += (double)smw[w * 6 + tid];
        g_partA[tid * NBLK_A + bid] = s;
    }
    __threadfence();
    __syncthreads();
    if (tid == 0) {
        unsigned int old = atomicInc(&g_cntA, NBLK_A - 1);
        lastBlk = (old == NBLK_A - 1);
    }
    __syncthreads();
    if (lastBlk) {
        for (int q = 0; q < 6; q++) {
            double s = 0.0;
            for (int i = tid; i < NBLK_A; i += 256) s += g_partA[q * NBLK_A + i];
            smd[tid] = s; __syncthreads();
            for (int st = 128; st > 0; st >>= 1) {
                if (tid < st) smd[tid] += smd[tid + st];
                __syncthreads();
            }
            if (tid == 0) g_sums[q] = smd[0];
            __syncthreads();
        }
    }
}

// ---------------- skeleton iteration: uint4 SWAR, 16 px/thread/row ----------
// state closed over {0,1,2}: e = (sum3x3 >= 9); out = e ? (c==1 ? 2 : 1) : 0
__device__ __forceinline__ void iterArrive(int dst) {
    __threadfence();
    unsigned int old = atomicInc(&g_cntI, GRID_I - 1);
    if (old == GRID_I - 1) {   // last block: folded flag logic
        for (int w = 0; w < 2; w++) {
            if (!g_done[w]) {
                if (g_curr[w] == g_prev[w]) g_done[w] = 1;   // ints: |d|<1 <=> equal
                g_prev[w] = g_curr[w];
                g_last[w] = dst;
            }
            g_curr[w] = 0ULL;
        }
    }
}

__global__ __launch_bounds__(256) void iterKernel(int src, int dst) {
    __shared__ int smi[8];

    const int tid = threadIdx.x;
    const int z = blockIdx.z;            // 0..31: 0..15 P, 16..31 T
    const int strip = blockIdx.x;        // rows [strip*32, +32)
    const int which = z >> 4;
    const int img = z & 15;

    if (g_done[which]) {                 // frozen plane: just participate in arrival
        if (tid == 0) iterArrive(dst);
        return;
    }

    const int g = tid >> 6;              // 0..3 row-groups of 8
    const int j = tid & 63;              // uint4 column 0..63
    const int lane = tid & 31;
    const int rowBase = strip * 32 + g * 8;
    const bool needL = (lane == 0) && (j > 0);
    const bool needR = (lane == 31) && (j < WPR4 - 1);

    const uint32_t* inw;
    uint32_t* outw;
    if (which == 0) {
        inw = (src == 0) ? g_binP : ((src == 1) ? g_wp0 : g_wp1);
        outw = (dst == 1) ? g_wp0 : g_wp1;
    } else {
        inw = (src == 0) ? g_binT : ((src == 1) ? g_wt0 : g_wt1);
        outw = (dst == 1) ? g_wt0 : g_wt1;
    }
    inw += (size_t)img * (HH * WPR);
    outw += (size_t)img * (HH * WPR);
    const uint4* in4 = (const uint4*)inw;
    uint4* out4 = (uint4*)outw;

    uint4 r0 = make_uint4(0u, 0u, 0u, 0u);
    if (rowBase > 0) r0 = in4[(rowBase - 1) * WPR4 + j];
    uint4 r1 = in4[rowBase * WPR4 + j];
    uint32_t l0 = 0, l1 = 0, q0 = 0, q1 = 0;
    if (needL) {
        if (rowBase > 0) l0 = inw[(rowBase - 1) * WPR + 4 * j - 1];
        l1 = inw[rowBase * WPR + 4 * j - 1];
    }
    if (needR) {
        if (rowBase > 0) q0 = inw[(rowBase - 1) * WPR + 4 * j + 4];
        q1 = inw[rowBase * WPR + 4 * j + 4];
    }

    int acc = 0;
#pragma unroll
    for (int y = rowBase; y < rowBase + 8; y++) {
        uint4 r2 = make_uint4(0u, 0u, 0u, 0u);
        if (y + 1 < HH) r2 = in4[(y + 1) * WPR4 + j];
        uint32_t l2 = 0, q2 = 0;
        if (needL && (y + 1 < HH)) l2 = inw[(y + 1) * WPR + 4 * j - 1];
        if (needR && (y + 1 < HH)) q2 = inw[(y + 1) * WPR + 4 * j + 4];

        uint32_t Vx = r0.x + r1.x + r2.x;
        uint32_t Vy = r0.y + r1.y + r2.y;
        uint32_t Vz = r0.z + r1.z + r2.z;
        uint32_t Vw = r0.w + r1.w + r2.w;
        uint32_t VL = __shfl_up_sync(0xFFFFFFFFu, Vw, 1);
        if (lane == 0) VL = l0 + l1 + l2;
        uint32_t VR = __shfl_down_sync(0xFFFFFFFFu, Vx, 1);
        if (lane == 31) VR = q0 + q1 + q2;

        uint32_t Hx = Vx + ((Vx >> 8) | (Vy << 24)) + ((Vx << 8) | (VL >> 24));
        uint32_t Hy = Vy + ((Vy >> 8) | (Vz << 24)) + ((Vy << 8) | (Vx >> 24));
        uint32_t Hz = Vz + ((Vz >> 8) | (Vw << 24)) + ((Vz << 8) | (Vy >> 24));
        uint32_t Hw = Vw + ((Vw >> 8) | (VR << 24)) + ((Vw << 8) | (Vz >> 24));

        uint4 o;
        uint32_t ge;
        ge = __vcmpgeu4(Hx, 0x09090909u);
        o.x = (ge & 0x01010101u) + (ge & __vcmpeq4(r1.x, 0x01010101u) & 0x01010101u);
        ge = __vcmpgeu4(Hy, 0x09090909u);
        o.y = (ge & 0x01010101u) + (ge & __vcmpeq4(r1.y, 0x01010101u) & 0x01010101u);
        ge = __vcmpgeu4(Hz, 0x09090909u);
        o.z = (ge & 0x01010101u) + (ge & __vcmpeq4(r1.z, 0x01010101u) & 0x01010101u);
        ge = __vcmpgeu4(Hw, 0x09090909u);
        o.w = (ge & 0x01010101u) + (ge & __vcmpeq4(r1.w, 0x01010101u) & 0x01010101u);

        out4[y * WPR4 + j] = o;
        acc = __dp4a(o.x, 0x01010101u, (unsigned int)acc);
        acc = __dp4a(o.y, 0x01010101u, (unsigned int)acc);
        acc = __dp4a(o.z, 0x01010101u, (unsigned int)acc);
        acc = __dp4a(o.w, 0x01010101u, (unsigned int)acc);

        r0 = r1; r1 = r2;
        l0 = l1; l1 = l2; q0 = q1; q1 = q2;
    }

#pragma unroll
    for (int o = 16; o > 0; o >>= 1) acc += __shfl_xor_sync(0xFFFFFFFFu, acc, o);
    if (lane == 0) smi[tid >> 5] = acc;
    __syncthreads();
    if (tid == 0) {
        int s = 0;
        for (int w = 0; w < 8; w++) s += smi[w];
        atomicAdd(&g_curr[which], (unsigned long long)s);
        iterArrive(dst);
    }
}

// ---------------- finalize: SWAR Sobel + skeleton dice (register sweep) ------
// Binary input => |gx|,|gy| <= 4; f = clip(skel + .5*sqrt(gx^2+gy^2+1e-8),0,1)
// quantizes: f = 1 if skel>=1 or g2>=4 else {0:5e-5, 1:.5, 2:.7071}[g2]
__global__ __launch_bounds__(256) void finKernel(float* __restrict__ out) {
    __shared__ float smw[24];
    __shared__ double smd[256];
    __shared__ double S3[3];
    __shared__ bool lastBlk;

    const int img = blockIdx.z;
    const int tid = threadIdx.x;
    const int lane = tid & 31, warp = tid >> 5;
    const int col = warp * 32 + lane;
    const int by = blockIdx.y * 16;

    const uint32_t* bP = g_binP + (size_t)img * (HH * WPR);
    const uint32_t* bT = g_binT + (size_t)img * (HH * WPR);
    const uint32_t* sp = ((g_last[0] == 1) ? g_wp0 : g_wp1) + (size_t)img * (HH * WPR);
    const uint32_t* st = ((g_last[1] == 1) ? g_wt0 : g_wt1) + (size_t)img * (HH * WPR);

    const bool isL = (lane == 0) && (col > 0);
    const bool isR = (lane == 31) && (col < WPR - 1);

    uint32_t p0 = (by > 0) ? bP[(by - 1) * WPR + col] : 0u;
    uint32_t p1 = bP[by * WPR + col];
    uint32_t t0 = (by > 0) ? bT[(by - 1) * WPR + col] : 0u;
    uint32_t t1 = bT[by * WPR + col];
    uint32_t lp0 = 0, lp1 = 0, lt0 = 0, lt1 = 0, rp0 = 0, rp1 = 0, rt0 = 0, rt1 = 0;
    if (isL) {
        lp0 = (by > 0) ? bP[(by - 1) * WPR + col - 1] : 0u; lp1 = bP[by * WPR + col - 1];
        lt0 = (by > 0) ? bT[(by - 1) * WPR + col - 1] : 0u; lt1 = bT[by * WPR + col - 1];
    }
    if (isR) {
        rp0 = (by > 0) ? bP[(by - 1) * WPR + col + 1] : 0u; rp1 = bP[by * WPR + col + 1];
        rt0 = (by > 0) ? bT[(by - 1) * WPR + col + 1] : 0u; rt1 = bT[by * WPR + col + 1];
    }

    float a0 = 0.f, a1 = 0.f, a2 = 0.f;
#pragma unroll 4
    for (int y = by; y < by + 16; y++) {
        uint32_t p2 = (y + 1 < HH) ? bP[(y + 1) * WPR + col] : 0u;
        uint32_t t2 = (y + 1 < HH) ? bT[(y + 1) * WPR + col] : 0u;
        uint32_t A_P = p0 + p1 + p1 + p2, B_P = p2 + (0x01010101u - p0);
        uint32_t A_T = t0 + t1 + t1 + t2, B_T = t2 + (0x01010101u - t0);

        uint32_t eAlP = 0u, eBlP = 0x01010101u, eAlT = 0u, eBlT = 0x01010101u;
        uint32_t eArP = 0u, eBrP = 0x01010101u, eArT = 0u, eBrT = 0x01010101u;
        if (isL) {
            uint32_t lp2 = (y + 1 < HH) ? bP[(y + 1) * WPR + col - 1] : 0u;
            uint32_t lt2 = (y + 1 < HH) ? bT[(y + 1) * WPR + col - 1] : 0u;
            eAlP = lp0 + lp1 + lp1 + lp2; eBlP = lp2 + (0x01010101u - lp0);
            eAlT = lt0 + lt1 + lt1 + lt2; eBlT = lt2 + (0x01010101u - lt0);
            lp0 = lp1; lp1 = lp2; lt0 = lt1; lt1 = lt2;
        }
        if (isR) {
            uint32_t rp2 = (y + 1 < HH) ? bP[(y + 1) * WPR + col + 1] : 0u;
            uint32_t rt2 = (y + 1 < HH) ? bT[(y + 1) * WPR + col + 1] : 0u;
            eArP = rp0 + rp1 + rp1 + rp2; eBrP = rp2 + (0x01010101u - rp0);
            eArT = rt0 + rt1 + rt1 + rt2; eBrT = rt2 + (0x01010101u - rt0);
            rp0 = rp1; rp1 = rp2; rt0 = rt1; rt1 = rt2;
        }

        uint32_t AlP = __shfl_up_sync(0xFFFFFFFFu, A_P, 1);   if (lane == 0)  AlP = eAlP;
        uint32_t ArP = __shfl_down_sync(0xFFFFFFFFu, A_P, 1); if (lane == 31) ArP = eArP;
        uint32_t BlP = __shfl_up_sync(0xFFFFFFFFu, B_P, 1);   if (lane == 0)  BlP = eBlP;
        uint32_t BrP = __shfl_down_sync(0xFFFFFFFFu, B_P, 1); if (lane == 31) BrP = eBrP;
        uint32_t AlT = __shfl_up_sync(0xFFFFFFFFu, A_T, 1);   if (lane == 0)  AlT = eAlT;
        uint32_t ArT = __shfl_down_sync(0xFFFFFFFFu, A_T, 1); if (lane == 31) ArT = eArT;
        uint32_t BlT = __shfl_up_sync(0xFFFFFFFFu, B_T, 1);   if (lane == 0)  BlT = eBlT;
        uint32_t BrT = __shfl_down_sync(0xFFFFFFFFu, B_T, 1); if (lane == 31) BrT = eBrT;

        uint32_t HxP = ((A_P >> 8) | (ArP << 24)) + (0x04040404u - ((A_P << 8) | (AlP >> 24)));
        uint32_t HyP = ((B_P << 8) | (BlP >> 24)) + B_P + B_P + ((B_P >> 8) | (BrP << 24));
        uint32_t HxT = ((A_T >> 8) | (ArT << 24)) + (0x04040404u - ((A_T << 8) | (AlT >> 24)));
        uint32_t HyT = ((B_T << 8) | (BlT >> 24)) + B_T + B_T + ((B_T >> 8) | (BrT << 24));

        uint32_t SP = sp[y * WPR + col];
        uint32_t ST = st[y * WPR + col];

#pragma unroll
        for (int b = 0; b < 4; b++) {
            int s = 8 * b;
            int gxp = (int)((HxP >> s) & 0xFF) - 4;
            int gyp = (int)((HyP >> s) & 0xFF) - 4;
            int g2p = gxp * gxp + gyp * gyp;
            int skp = (int)((SP >> s) & 0xFF);
            float fP = (skp | (g2p >= 4)) ? 1.0f
                     : (g2p == 0 ? 5.0e-5f : (g2p == 1 ? 0.5f : 0.70710678f));

            int gxt = (int)((HxT >> s) & 0xFF) - 4;
            int gyt = (int)((HyT >> s) & 0xFF) - 4;
            int g2t = gxt * gxt + gyt * gyt;
            int skt = (int)((ST >> s) & 0xFF);
            float fT = (skt | (g2t >= 4)) ? 1.0f
                     : (g2t == 0 ? 5.0e-5f : (g2t == 1 ? 0.5f : 0.70710678f));

            a0 += fP; a1 += fT; a2 += fP * fT;
        }
        p0 = p1; p1 = p2; t0 = t1; t1 = t2;
    }

    float vals[3] = {a0, a1, a2};
#pragma unroll
    for (int q = 0; q < 3; q++) {
        float v = vals[q];
#pragma unroll
        for (int o = 16; o > 0; o >>= 1) v += __shfl_xor_sync(0xFFFFFFFFu, v, o);
        if (lane == 0) smw[warp * 3 + q] = v;
    }
    __syncthreads();
    int bid = blockIdx.z * gridDim.y + blockIdx.y;
    if (tid < 3) {
        double sm = 0.0;
        for (int w = 0; w < 8; w++) sm += (double)smw[w * 3 + tid];
        g_partF[tid * NBLK_F + bid] = sm;
    }
    __threadfence();
    __syncthreads();
    if (tid == 0) {
        unsigned int old = atomicInc(&g_cntF, NBLK_F - 1);
        lastBlk = (old == NBLK_F - 1);
    }
    __syncthreads();
    if (lastBlk) {
        for (int q = 0; q < 3; q++) {
            double s = 0.0;
            for (int i = tid; i < NBLK_F; i += 256) s += g_partF[q * NBLK_F + i];
            smd[tid] = s; __syncthreads();
            for (int stp = 128; stp > 0; stp >>= 1) {
                if (tid < stp) smd[tid] += smd[tid + stp];
                __syncthreads();
            }
            if (tid == 0) S3[q] = smd[0];
            __syncthreads();
        }
        if (tid == 0) {
            double Sp = g_sums[0], St = g_sums[1], Spt = g_sums[2];
            double Sf = g_sums[3], Sc = g_sums[4], nw = g_sums[5];
            double S6 = S3[0], S7 = S3[1], S8 = S3[2];

            double skel_dice = (2.0 * S8 + 1.0) / (S6 + S7 + 1.0);
            double skeleton = 1.0 - skel_dice;
            double dice = 1.0 - (2.0 * Spt + 1.0) / (Sp + St + 1.0);
            double focal = Sf / (double)NPIX;
            focal = fmin(fmax(focal, 0.0), 10.0);
            double conn = (nw == 0.0) ? 0.0 : (Sc / fmax(nw, 1.0));

            double total = 0.3 * skeleton + 0.4 * dice + 0.2 * focal + 0.1 * conn;
            if (isnan(total) || isinf(total)) total = dice;
            out[0] = (float)total;
        }
    }
}

// ---------------- launch -----------------------------------------------------
extern "C" void kernel_launch(void* const* d_in, const int* in_sizes, int n_in,
                              void* d_out, int out_size) {
    const float* pred = (const float*)d_in[0];
    const float* target = (const float*)d_in[1];
    float* out = (float*)d_out;

    dim3 blk(256);
    dim3 grdA(4, 32, 16);    // 256-col x 32-row strips, batch
    dim3 grdI(32, 1, 32);    // 32 row-strips of 32; z: 0..15 P, 16..31 T
    dim3 grdF(1, 64, 16);    // full-width x 16-row strips, batch

    initKernel<<<1, 1>>>();
    mainKernel<<<grdA, blk>>>(pred, target);

    for (int i = 0; i < 10; i++) {
        int src = (i == 0) ? 0 : ((i % 2 == 0) ? 2 : 1);  // 0=bin, 1=w0, 2=w1
        int dst = (i % 2 == 0) ? 1 : 2;
        iterKernel<<<grdI, blk>>>(src, dst);
    }

    finKernel<<<grdF, blk>>>(out);
}

// round 7
// speedup vs baseline: 4.1049x; 1.2990x over previous
#include <cuda_runtime.h>
#include <math.h>
#include <stdint.h>

// Shapes fixed by the problem: [16, 1, 1024, 1024] float32
#define BB 16
#define HH 1024
#define WW 1024
#define WPR 256                       // uint32 words per row (1024/4)
#define WPR4 64                       // uint4 per row
#define NPIX (BB * HH * WW)           // 16777216
#define NWORD (NPIX / 4)
#define NBLK_A 1024                   // main grid blocks (64 strips * 16)
#define NBLK_F 1024                   // fin grid blocks (64*16)
#define GRID_I 2048                   // iter grid blocks (64 strips * 32 z)

// ---------------- device scratch (no runtime allocation) ---------------------
__device__ uint32_t g_binP[NWORD];    // binary(pred_prob), 1 byte/pixel
__device__ uint32_t g_binT[NWORD];    // binary(target)
__device__ uint32_t g_wp0[NWORD];     // skeleton ping-pong (pred)
__device__ uint32_t g_wp1[NWORD];
__device__ uint32_t g_wt0[NWORD];     // skeleton ping-pong (target)
__device__ uint32_t g_wt1[NWORD];

__device__ double g_partA[6 * NBLK_A];
__device__ double g_partF[3 * NBLK_F];

__device__ unsigned long long g_curr[2];
__device__ unsigned long long g_prev[2];
__device__ int g_done[2];
__device__ int g_last[2];             // 1 -> wX0, 2 -> wX1 holds final skeleton
__device__ unsigned int g_cntA;
__device__ unsigned int g_cntF;
__device__ unsigned int g_cntI;       // iter arrival counter (self-reset via wrap)
__device__ double g_sums[6];          // Sp,St,Spt,Sfocal,Sconn,nwater

__device__ __forceinline__ float sigm_fast(float x) {
    return __fdividef(1.0f, 1.0f + __expf(-x));
}

// ---------------- pass 1: fused elementwise + connectivity (float4 sweep) ----
// Block: 8 warps cover the full 1024-px row width (warp w -> cols [128w,128w+128),
// lane -> 4 px). Block sweeps 16 rows. Last block folds the cross-block
// reduction AND the iteration-state init (safe: stream order).
__global__ __launch_bounds__(256) void mainKernel(const float* __restrict__ pred,
                                                  const float* __restrict__ target) {
    __shared__ float smw[48];
    __shared__ double smd[256];
    __shared__ bool lastBlk;

    const int img = blockIdx.z;
    const int tid = threadIdx.x;
    const int lane = tid & 31, warp = tid >> 5;
    const int c = warp * 128 + lane * 4;            // first pixel column
    const int by = blockIdx.y * 16;
    const float* pimg = pred + (size_t)img * HH * WW;
    const float* timg = target + (size_t)img * HH * WW;
    uint32_t* bP32 = g_binP + (size_t)img * (HH * WPR);
    uint32_t* bT32 = g_binT + (size_t)img * (HH * WPR);
    const bool isL = (lane == 0) && (c > 0);        // needs col c-1 (cross-warp)
    const bool isR = (lane == 31) && (c + 4 < WW);  // needs col c+4

    float d0[4], d1[4], d2[4], p1[4], t1[4];
    // prologue: rows by-1 and by
    {
        if (by > 0) {
            float4 pv = *reinterpret_cast<const float4*>(pimg + (by - 1) * WW + c);
            float4 tv = *reinterpret_cast<const float4*>(timg + (by - 1) * WW + c);
            d0[0] = sigm_fast(pv.x) - tv.x; d0[1] = sigm_fast(pv.y) - tv.y;
            d0[2] = sigm_fast(pv.z) - tv.z; d0[3] = sigm_fast(pv.w) - tv.w;
        } else { d0[0] = d0[1] = d0[2] = d0[3] = 0.f; }
        float4 pv = *reinterpret_cast<const float4*>(pimg + by * WW + c);
        float4 tv = *reinterpret_cast<const float4*>(timg + by * WW + c);
        p1[0] = sigm_fast(pv.x); p1[1] = sigm_fast(pv.y);
        p1[2] = sigm_fast(pv.z); p1[3] = sigm_fast(pv.w);
        t1[0] = tv.x; t1[1] = tv.y; t1[2] = tv.z; t1[3] = tv.w;
#pragma unroll
        for (int i = 0; i < 4; i++) d1[i] = p1[i] - t1[i];
    }
    float dl0 = 0.f, dl1 = 0.f, dr0 = 0.f, dr1 = 0.f;
    if (isL) {
        if (by > 0) dl0 = sigm_fast(pimg[(by - 1) * WW + c - 1]) - timg[(by - 1) * WW + c - 1];
        dl1 = sigm_fast(pimg[by * WW + c - 1]) - timg[by * WW + c - 1];
    }
    if (isR) {
        if (by > 0) dr0 = sigm_fast(pimg[(by - 1) * WW + c + 4]) - timg[(by - 1) * WW + c + 4];
        dr1 = sigm_fast(pimg[by * WW + c + 4]) - timg[by * WW + c + 4];
    }

    float a0 = 0.f, a1 = 0.f, a2 = 0.f, a3 = 0.f, a4 = 0.f, a5 = 0.f;
#pragma unroll 2
    for (int y = by; y < by + 16; y++) {
        float p2[4], t2[4];
        if (y + 1 < HH) {
            float4 pv = *reinterpret_cast<const float4*>(pimg + (y + 1) * WW + c);
            float4 tv = *reinterpret_cast<const float4*>(timg + (y + 1) * WW + c);
            p2[0] = sigm_fast(pv.x); p2[1] = sigm_fast(pv.y);
            p2[2] = sigm_fast(pv.z); p2[3] = sigm_fast(pv.w);
            t2[0] = tv.x; t2[1] = tv.y; t2[2] = tv.z; t2[3] = tv.w;
        } else {
#pragma unroll
            for (int i = 0; i < 4; i++) { p2[i] = 0.f; t2[i] = 0.f; }
        }
#pragma unroll
        for (int i = 0; i < 4; i++) d2[i] = p2[i] - t2[i];

        float VcL = 0.f, VcR = 0.f;
        if (isL) {
            float dl2 = (y + 1 < HH)
                ? sigm_fast(pimg[(y + 1) * WW + c - 1]) - timg[(y + 1) * WW + c - 1] : 0.f;
            VcL = dl0 + dl1 + dl2; dl0 = dl1; dl1 = dl2;
        }
        if (isR) {
            float dr2 = (y + 1 < HH)
                ? sigm_fast(pimg[(y + 1) * WW + c + 4]) - timg[(y + 1) * WW + c + 4] : 0.f;
            VcR = dr0 + dr1 + dr2; dr0 = dr1; dr1 = dr2;
        }

        float V[4];
#pragma unroll
        for (int i = 0; i < 4; i++) V[i] = d0[i] + d1[i] + d2[i];
        float Vlm = __shfl_up_sync(0xFFFFFFFFu, V[3], 1);   if (lane == 0)  Vlm = VcL;
        float Vrp = __shfl_down_sync(0xFFFFFFFFu, V[0], 1); if (lane == 31) Vrp = VcR;
        float H[4];
        H[0] = Vlm + V[0] + V[1];
        H[1] = V[0] + V[1] + V[2];
        H[2] = V[1] + V[2] + V[3];
        H[3] = V[2] + V[3] + Vrp;

        uint32_t bpw = 0, btw = 0;
#pragma unroll
        for (int i = 0; i < 4; i++) {
            float p = p1[i], t = t1[i];
            bool bp = (p > 0.5f);
            bool bt = (t > 0.5f);
            bpw |= ((uint32_t)bp) << (8 * i);
            btw |= ((uint32_t)bt) << (8 * i);

            a0 += p; a1 += t; a2 += p * t;

            // focal (gamma=2, alpha=0.25), t in {0,1} exact
            float pc = fminf(fmaxf(p, 1e-6f), 1.0f - 1e-6f);
            bool one = (t == 1.0f);
            float pt = one ? pc : (1.0f - pc);
            float bce = -__logf(pt);
            float fw = (1.0f - pt) * (1.0f - pt);
            float at = one ? 0.25f : 0.75f;
            a3 += at * fw * bce;

            float v = H[i] * (1.0f / 9.0f);
            if (bt) { a4 += v * v; a5 += 1.0f; }
        }
        bP32[y * WPR + (c >> 2)] = bpw;
        bT32[y * WPR + (c >> 2)] = btw;

#pragma unroll
        for (int i = 0; i < 4; i++) {
            d0[i] = d1[i]; d1[i] = d2[i];
            p1[i] = p2[i]; t1[i] = t2[i];
        }
    }

    // warp-shuffle reduction
    float vals[6] = {a0, a1, a2, a3, a4, a5};
#pragma unroll
    for (int q = 0; q < 6; q++) {
        float v = vals[q];
#pragma unroll
        for (int o = 16; o > 0; o >>= 1) v += __shfl_xor_sync(0xFFFFFFFFu, v, o);
        if (lane == 0) smw[warp * 6 + q] = v;
    }
    __syncthreads();
    int bid = blockIdx.z * gridDim.y + blockIdx.y;
    if (tid < 6) {
        double s = 0.0;
        for (int w = 0; w < 8; w++) s += (double)smw[w * 6 + tid];
        g_partA[tid * NBLK_A + bid] = s;
    }
    __threadfence();
    __syncthreads();
    if (tid == 0) {
        unsigned int old = atomicInc(&g_cntA, NBLK_A - 1);
        lastBlk = (old == NBLK_A - 1);
    }
    __syncthreads();
    if (lastBlk) {
        for (int q = 0; q < 6; q++) {
            double s = 0.0;
            for (int i = tid; i < NBLK_A; i += 256) s += g_partA[q * NBLK_A + i];
            smd[tid] = s; __syncthreads();
            for (int st = 128; st > 0; st >>= 1) {
                if (tid < st) smd[tid] += smd[tid + st];
                __syncthreads();
            }
            if (tid == 0) g_sums[q] = smd[0];
            __syncthreads();
        }
        if (tid == 0) {   // folded init of iteration state (pre-iterKernel)
            g_curr[0] = g_curr[1] = 0ULL;
            g_prev[0] = g_prev[1] = 0xFFFFFFFFFFFFFFFFULL;
            g_done[0] = g_done[1] = 0;
            g_last[0] = g_last[1] = 1;
        }
    }
}

// ---------------- skeleton iteration: uint4 SWAR, 16 px/thread/row ----------
// state closed over {0,1,2}: e = (sum3x3 >= 9); out = e ? (c==1 ? 2 : 1) : 0
__device__ __forceinline__ void iterArrive(int dst) {
    __threadfence();
    unsigned int old = atomicInc(&g_cntI, GRID_I - 1);
    if (old == GRID_I - 1) {   // last block: folded flag logic
        for (int w = 0; w < 2; w++) {
            if (!g_done[w]) {
                if (g_curr[w] == g_prev[w]) g_done[w] = 1;   // ints: |d|<1 <=> equal
                g_prev[w] = g_curr[w];
                g_last[w] = dst;
            }
            g_curr[w] = 0ULL;
        }
    }
}

__global__ __launch_bounds__(256) void iterKernel(int src, int dst) {
    __shared__ int smi[8];

    const int tid = threadIdx.x;
    const int z = blockIdx.z;            // 0..31: 0..15 P, 16..31 T
    const int strip = blockIdx.x;        // rows [strip*16, +16)
    const int which = z >> 4;
    const int img = z & 15;

    if (g_done[which]) {                 // frozen plane: just participate in arrival
        if (tid == 0) iterArrive(dst);
        return;
    }

    const int g = tid >> 6;              // 0..3 row-groups of 4
    const int j = tid & 63;              // uint4 column 0..63
    const int lane = tid & 31;
    const int rowBase = strip * 16 + g * 4;
    const bool needL = (lane == 0) && (j > 0);
    const bool needR = (lane == 31) && (j < WPR4 - 1);

    const uint32_t* inw;
    uint32_t* outw;
    if (which == 0) {
        inw = (src == 0) ? g_binP : ((src == 1) ? g_wp0 : g_wp1);
        outw = (dst == 1) ? g_wp0 : g_wp1;
    } else {
        inw = (src == 0) ? g_binT : ((src == 1) ? g_wt0 : g_wt1);
        outw = (dst == 1) ? g_wt0 : g_wt1;
    }
    inw += (size_t)img * (HH * WPR);
    outw += (size_t)img * (HH * WPR);
    const uint4* in4 = (const uint4*)inw;
    uint4* out4 = (uint4*)outw;

    uint4 r0 = make_uint4(0u, 0u, 0u, 0u);
    if (rowBase > 0) r0 = in4[(rowBase - 1) * WPR4 + j];
    uint4 r1 = in4[rowBase * WPR4 + j];
    uint32_t l0 = 0, l1 = 0, q0 = 0, q1 = 0;
    if (needL) {
        if (rowBase > 0) l0 = inw[(rowBase - 1) * WPR + 4 * j - 1];
        l1 = inw[rowBase * WPR + 4 * j - 1];
    }
    if (needR) {
        if (rowBase > 0) q0 = inw[(rowBase - 1) * WPR + 4 * j + 4];
        q1 = inw[rowBase * WPR + 4 * j + 4];
    }

    int acc = 0;
#pragma unroll
    for (int y = rowBase; y < rowBase + 4; y++) {
        uint4 r2 = make_uint4(0u, 0u, 0u, 0u);
        if (y + 1 < HH) r2 = in4[(y + 1) * WPR4 + j];
        uint32_t l2 = 0, q2 = 0;
        if (needL && (y + 1 < HH)) l2 = inw[(y + 1) * WPR + 4 * j - 1];
        if (needR && (y + 1 < HH)) q2 = inw[(y + 1) * WPR + 4 * j + 4];

        uint32_t Vx = r0.x + r1.x + r2.x;
        uint32_t Vy = r0.y + r1.y + r2.y;
        uint32_t Vz = r0.z + r1.z + r2.z;
        uint32_t Vw = r0.w + r1.w + r2.w;
        uint32_t VL = __shfl_up_sync(0xFFFFFFFFu, Vw, 1);
        if (lane == 0) VL = l0 + l1 + l2;
        uint32_t VR = __shfl_down_sync(0xFFFFFFFFu, Vx, 1);
        if (lane == 31) VR = q0 + q1 + q2;

        uint32_t Hx = Vx + ((Vx >> 8) | (Vy << 24)) + ((Vx << 8) | (VL >> 24));
        uint32_t Hy = Vy + ((Vy >> 8) | (Vz << 24)) + ((Vy << 8) | (Vx >> 24));
        uint32_t Hz = Vz + ((Vz >> 8) | (Vw << 24)) + ((Vz << 8) | (Vy >> 24));
        uint32_t Hw = Vw + ((Vw >> 8) | (VR << 24)) + ((Vw << 8) | (Vz >> 24));

        uint4 o;
        uint32_t ge;
        ge = __vcmpgeu4(Hx, 0x09090909u);
        o.x = (ge & 0x01010101u) + (ge & __vcmpeq4(r1.x, 0x01010101u) & 0x01010101u);
        ge = __vcmpgeu4(Hy, 0x09090909u);
        o.y = (ge & 0x01010101u) + (ge & __vcmpeq4(r1.y, 0x01010101u) & 0x01010101u);
        ge = __vcmpgeu4(Hz, 0x09090909u);
        o.z = (ge & 0x01010101u) + (ge & __vcmpeq4(r1.z, 0x01010101u) & 0x01010101u);
        ge = __vcmpgeu4(Hw, 0x09090909u);
        o.w = (ge & 0x01010101u) + (ge & __vcmpeq4(r1.w, 0x01010101u) & 0x01010101u);

        out4[y * WPR4 + j] = o;
        acc = __dp4a(o.x, 0x01010101u, (unsigned int)acc);
        acc = __dp4a(o.y, 0x01010101u, (unsigned int)acc);
        acc = __dp4a(o.z, 0x01010101u, (unsigned int)acc);
        acc = __dp4a(o.w, 0x01010101u, (unsigned int)acc);

        r0 = r1; r1 = r2;
        l0 = l1; l1 = l2; q0 = q1; q1 = q2;
    }

#pragma unroll
    for (int o = 16; o > 0; o >>= 1) acc += __shfl_xor_sync(0xFFFFFFFFu, acc, o);
    if (lane == 0) smi[tid >> 5] = acc;
    __syncthreads();
    if (tid == 0) {
        int s = 0;
        for (int w = 0; w < 8; w++) s += smi[w];
        atomicAdd(&g_curr[which], (unsigned long long)s);
        iterArrive(dst);
    }
}

// ---------------- finalize: SWAR Sobel + skeleton dice (register sweep) ------
// Binary input => |gx|,|gy| <= 4; f = clip(skel + .5*sqrt(gx^2+gy^2+1e-8),0,1)
// quantizes: f = 1 if skel>=1 or g2>=4 else {0:5e-5, 1:.5, 2:.7071}[g2]
__global__ __launch_bounds__(256) void finKernel(float* __restrict__ out) {
    __shared__ float smw[24];
    __shared__ double smd[256];
    __shared__ double S3[3];
    __shared__ bool lastBlk;

    const int img = blockIdx.z;
    const int tid = threadIdx.x;
    const int lane = tid & 31, warp = tid >> 5;
    const int col = warp * 32 + lane;
    const int by = blockIdx.y * 16;

    const uint32_t* bP = g_binP + (size_t)img * (HH * WPR);
    const uint32_t* bT = g_binT + (size_t)img * (HH * WPR);
    const uint32_t* sp = ((g_last[0] == 1) ? g_wp0 : g_wp1) + (size_t)img * (HH * WPR);
    const uint32_t* st = ((g_last[1] == 1) ? g_wt0 : g_wt1) + (size_t)img * (HH * WPR);

    const bool isL = (lane == 0) && (col > 0);
    const bool isR = (lane == 31) && (col < WPR - 1);

    uint32_t p0 = (by > 0) ? bP[(by - 1) * WPR + col] : 0u;
    uint32_t p1 = bP[by * WPR + col];
    uint32_t t0 = (by > 0) ? bT[(by - 1) * WPR + col] : 0u;
    uint32_t t1 = bT[by * WPR + col];
    uint32_t lp0 = 0, lp1 = 0, lt0 = 0, lt1 = 0, rp0 = 0, rp1 = 0, rt0 = 0, rt1 = 0;
    if (isL) {
        lp0 = (by > 0) ? bP[(by - 1) * WPR + col - 1] : 0u; lp1 = bP[by * WPR + col - 1];
        lt0 = (by > 0) ? bT[(by - 1) * WPR + col - 1] : 0u; lt1 = bT[by * WPR + col - 1];
    }
    if (isR) {
        rp0 = (by > 0) ? bP[(by - 1) * WPR + col + 1] : 0u; rp1 = bP[by * WPR + col + 1];
        rt0 = (by > 0) ? bT[(by - 1) * WPR + col + 1] : 0u; rt1 = bT[by * WPR + col + 1];
    }

    float a0 = 0.f, a1 = 0.f, a2 = 0.f;
#pragma unroll 4
    for (int y = by; y < by + 16; y++) {
        uint32_t p2 = (y + 1 < HH) ? bP[(y + 1) * WPR + col] : 0u;
        uint32_t t2 = (y + 1 < HH) ? bT[(y + 1) * WPR + col] : 0u;
        uint32_t A_P = p0 + p1 + p1 + p2, B_P = p2 + (0x01010101u - p0);
        uint32_t A_T = t0 + t1 + t1 + t2, B_T = t2 + (0x01010101u - t0);

        uint32_t eAlP = 0u, eBlP = 0x01010101u, eAlT = 0u, eBlT = 0x01010101u;
        uint32_t eArP = 0u, eBrP = 0x01010101u, eArT = 0u, eBrT = 0x01010101u;
        if (isL) {
            uint32_t lp2 = (y + 1 < HH) ? bP[(y + 1) * WPR + col - 1] : 0u;
            uint32_t lt2 = (y + 1 < HH) ? bT[(y + 1) * WPR + col - 1] : 0u;
            eAlP = lp0 + lp1 + lp1 + lp2; eBlP = lp2 + (0x01010101u - lp0);
            eAlT = lt0 + lt1 + lt1 + lt2; eBlT = lt2 + (0x01010101u - lt0);
            lp0 = lp1; lp1 = lp2; lt0 = lt1; lt1 = lt2;
        }
        if (isR) {
            uint32_t rp2 = (y + 1 < HH) ? bP[(y + 1) * WPR + col + 1] : 0u;
            uint32_t rt2 = (y + 1 < HH) ? bT[(y + 1) * WPR + col + 1] : 0u;
            eArP = rp0 + rp1 + rp1 + rp2; eBrP = rp2 + (0x01010101u - rp0);
            eArT = rt0 + rt1 + rt1 + rt2; eBrT = rt2 + (0x01010101u - rt0);
            rp0 = rp1; rp1 = rp2; rt0 = rt1; rt1 = rt2;
        }

        uint32_t AlP = __shfl_up_sync(0xFFFFFFFFu, A_P, 1);   if (lane == 0)  AlP = eAlP;
        uint32_t ArP = __shfl_down_sync(0xFFFFFFFFu, A_P, 1); if (lane == 31) ArP = eArP;
        uint32_t BlP = __shfl_up_sync(0xFFFFFFFFu, B_P, 1);   if (lane == 0)  BlP = eBlP;
        uint32_t BrP = __shfl_down_sync(0xFFFFFFFFu, B_P, 1); if (lane == 31) BrP = eBrP;
        uint32_t AlT = __shfl_up_sync(0xFFFFFFFFu, A_T, 1);   if (lane == 0)  AlT = eAlT;
        uint32_t ArT = __shfl_down_sync(0xFFFFFFFFu, A_T, 1); if (lane == 31) ArT = eArT;
        uint32_t BlT = __shfl_up_sync(0xFFFFFFFFu, B_T, 1);   if (lane == 0)  BlT = eBlT;
        uint32_t BrT = __shfl_down_sync(0xFFFFFFFFu, B_T, 1); if (lane == 31) BrT = eBrT;

        uint32_t HxP = ((A_P >> 8) | (ArP << 24)) + (0x04040404u - ((A_P << 8) | (AlP >> 24)));
        uint32_t HyP = ((B_P << 8) | (BlP >> 24)) + B_P + B_P + ((B_P >> 8) | (BrP << 24));
        uint32_t HxT = ((A_T >> 8) | (ArT << 24)) + (0x04040404u - ((A_T << 8) | (AlT >> 24)));
        uint32_t HyT = ((B_T << 8) | (BlT >> 24)) + B_T + B_T + ((B_T >> 8) | (BrT << 24));

        uint32_t SP = sp[y * WPR + col];
        uint32_t ST = st[y * WPR + col];

#pragma unroll
        for (int b = 0; b < 4; b++) {
            int s = 8 * b;
            int gxp = (int)((HxP >> s) & 0xFF) - 4;
            int gyp = (int)((HyP >> s) & 0xFF) - 4;
            int g2p = gxp * gxp + gyp * gyp;
            int skp = (int)((SP >> s) & 0xFF);
            float fP = (skp | (g2p >= 4)) ? 1.0f
                     : (g2p == 0 ? 5.0e-5f : (g2p == 1 ? 0.5f : 0.70710678f));

            int gxt = (int)((HxT >> s) & 0xFF) - 4;
            int gyt = (int)((HyT >> s) & 0xFF) - 4;
            int g2t = gxt * gxt + gyt * gyt;
            int skt = (int)((ST >> s) & 0xFF);
            float fT = (skt | (g2t >= 4)) ? 1.0f
                     : (g2t == 0 ? 5.0e-5f : (g2t == 1 ? 0.5f : 0.70710678f));

            a0 += fP; a1 += fT; a2 += fP * fT;
        }
        p0 = p1; p1 = p2; t0 = t1; t1 = t2;
    }

    float vals[3] = {a0, a1, a2};
#pragma unroll
    for (int q = 0; q < 3; q++) {
        float v = vals[q];
#pragma unroll
        for (int o = 16; o > 0; o >>= 1) v += __shfl_xor_sync(0xFFFFFFFFu, v, o);
        if (lane == 0) smw[warp * 3 + q] = v;
    }
    __syncthreads();
    int bid = blockIdx.z * gridDim.y + blockIdx.y;
    if (tid < 3) {
        double sm = 0.0;
        for (int w = 0; w < 8; w++) sm += (double)smw[w * 3 + tid];
        g_partF[tid * NBLK_F + bid] = sm;
    }
    __threadfence();
    __syncthreads();
    if (tid == 0) {
        unsigned int old = atomicInc(&g_cntF, NBLK_F - 1);
        lastBlk = (old == NBLK_F - 1);
    }
    __syncthreads();
    if (lastBlk) {
        for (int q = 0; q < 3; q++) {
            double s = 0.0;
            for (int i = tid; i < NBLK_F; i += 256) s += g_partF[q * NBLK_F + i];
            smd[tid] = s; __syncthreads();
            for (int stp = 128; stp > 0; stp >>= 1) {
                if (tid < stp) smd[tid] += smd[tid + stp];
                __syncthreads();
            }
            if (tid == 0) S3[q] = smd[0];
            __syncthreads();
        }
        if (tid == 0) {
            double Sp = g_sums[0], St = g_sums[1], Spt = g_sums[2];
            double Sf = g_sums[3], Sc = g_sums[4], nw = g_sums[5];
            double S6 = S3[0], S7 = S3[1], S8 = S3[2];

            double skel_dice = (2.0 * S8 + 1.0) / (S6 + S7 + 1.0);
            double skeleton = 1.0 - skel_dice;
            double dice = 1.0 - (2.0 * Spt + 1.0) / (Sp + St + 1.0);
            double focal = Sf / (double)NPIX;
            focal = fmin(fmax(focal, 0.0), 10.0);
            double conn = (nw == 0.0) ? 0.0 : (Sc / fmax(nw, 1.0));

            double total = 0.3 * skeleton + 0.4 * dice + 0.2 * focal + 0.1 * conn;
            if (isnan(total) || isinf(total)) total = dice;
            out[0] = (float)total;
        }
    }
}

// ---------------- launch -----------------------------------------------------
extern "C" void kernel_launch(void* const* d_in, const int* in_sizes, int n_in,
                              void* d_out, int out_size) {
    const float* pred = (const float*)d_in[0];
    const float* target = (const float*)d_in[1];
    float* out = (float*)d_out;

    dim3 blk(256);
    dim3 grdA(1, 64, 16);    // full-width x 16-row strips, batch
    dim3 grdI(64, 1, 32);    // 64 row-strips of 16; z: 0..15 P, 16..31 T
    dim3 grdF(1, 64, 16);    // full-width x 16-row strips, batch

    mainKernel<<<grdA, blk>>>(pred, target);

    for (int i = 0; i < 10; i++) {
        int src = (i == 0) ? 0 : ((i % 2 == 0) ? 2 : 1);  // 0=bin, 1=w0, 2=w1
        int dst = (i % 2 == 0) ? 1 : 2;
        iterKernel<<<grdI, blk>>>(src, dst);
    }

    finKernel<<<grdF, blk>>>(out);
}

// round 8
// speedup vs baseline: 4.3718x; 1.0650x over previous
#include <cuda_runtime.h>
#include <math.h>
#include <stdint.h>

// Shapes fixed by the problem: [16, 1, 1024, 1024] float32
#define BB 16
#define HH 1024
#define WW 1024
#define WPR 256                       // uint32 words per row (1024/4)
#define WPR4 64                       // uint4 per row
#define NPIX (BB * HH * WW)           // 16777216
#define NWORD (NPIX / 4)
#define NBLK_A 1024                   // main grid blocks (64 strips * 16)
#define NBLK_F 1024                   // fin grid blocks (64*16)
#define GRID_I2 1024                  // iter2 grid blocks (32 strips * 32 z)

// ---------------- device scratch (no runtime allocation) ---------------------
__device__ uint32_t g_binP[NWORD];    // binary(pred_prob), 1 byte/pixel
__device__ uint32_t g_binT[NWORD];    // binary(target)
__device__ uint32_t g_wp0[NWORD];     // skeleton buffers (pred): 0 = step-A, 1/2 = step-B ping-pong
__device__ uint32_t g_wp1[NWORD];
__device__ uint32_t g_wp2[NWORD];
__device__ uint32_t g_wt0[NWORD];     // same for target
__device__ uint32_t g_wt1[NWORD];
__device__ uint32_t g_wt2[NWORD];

__device__ double g_partA[6 * NBLK_A];
__device__ double g_partF[3 * NBLK_F];

__device__ unsigned long long g_currA[2];  // per-double-launch sums (step A, step B)
__device__ unsigned long long g_currB[2];
__device__ unsigned long long g_prev[2];
__device__ int g_done[2];
__device__ int g_last[2];             // 0 -> wX0(A), 1 -> wX1, 2 -> wX2 holds final skeleton
__device__ unsigned int g_cntA;
__device__ unsigned int g_cntF;
__device__ unsigned int g_cntI;       // iter arrival counter (self-reset via wrap)
__device__ double g_sums[6];          // Sp,St,Spt,Sfocal,Sconn,nwater

__device__ __forceinline__ float sigm_fast(float x) {
    return __fdividef(1.0f, 1.0f + __expf(-x));
}

// ---------------- pass 1: fused elementwise + connectivity (float4 sweep) ----
__global__ __launch_bounds__(256) void mainKernel(const float* __restrict__ pred,
                                                  const float* __restrict__ target) {
    __shared__ float smw[48];
    __shared__ double smd[256];
    __shared__ bool lastBlk;

    const int img = blockIdx.z;
    const int tid = threadIdx.x;
    const int lane = tid & 31, warp = tid >> 5;
    const int c = warp * 128 + lane * 4;            // first pixel column
    const int by = blockIdx.y * 16;
    const float* pimg = pred + (size_t)img * HH * WW;
    const float* timg = target + (size_t)img * HH * WW;
    uint32_t* bP32 = g_binP + (size_t)img * (HH * WPR);
    uint32_t* bT32 = g_binT + (size_t)img * (HH * WPR);
    const bool isL = (lane == 0) && (c > 0);
    const bool isR = (lane == 31) && (c + 4 < WW);

    float d0[4], d1[4], d2[4], p1[4], t1[4];
    {
        if (by > 0) {
            float4 pv = *reinterpret_cast<const float4*>(pimg + (by - 1) * WW + c);
            float4 tv = *reinterpret_cast<const float4*>(timg + (by - 1) * WW + c);
            d0[0] = sigm_fast(pv.x) - tv.x; d0[1] = sigm_fast(pv.y) - tv.y;
            d0[2] = sigm_fast(pv.z) - tv.z; d0[3] = sigm_fast(pv.w) - tv.w;
        } else { d0[0] = d0[1] = d0[2] = d0[3] = 0.f; }
        float4 pv = *reinterpret_cast<const float4*>(pimg + by * WW + c);
        float4 tv = *reinterpret_cast<const float4*>(timg + by * WW + c);
        p1[0] = sigm_fast(pv.x); p1[1] = sigm_fast(pv.y);
        p1[2] = sigm_fast(pv.z); p1[3] = sigm_fast(pv.w);
        t1[0] = tv.x; t1[1] = tv.y; t1[2] = tv.z; t1[3] = tv.w;
#pragma unroll
        for (int i = 0; i < 4; i++) d1[i] = p1[i] - t1[i];
    }
    float dl0 = 0.f, dl1 = 0.f, dr0 = 0.f, dr1 = 0.f;
    if (isL) {
        if (by > 0) dl0 = sigm_fast(pimg[(by - 1) * WW + c - 1]) - timg[(by - 1) * WW + c - 1];
        dl1 = sigm_fast(pimg[by * WW + c - 1]) - timg[by * WW + c - 1];
    }
    if (isR) {
        if (by > 0) dr0 = sigm_fast(pimg[(by - 1) * WW + c + 4]) - timg[(by - 1) * WW + c + 4];
        dr1 = sigm_fast(pimg[by * WW + c + 4]) - timg[by * WW + c + 4];
    }

    float a0 = 0.f, a1 = 0.f, a2 = 0.f, a3 = 0.f, a4 = 0.f, a5 = 0.f;
#pragma unroll 2
    for (int y = by; y < by + 16; y++) {
        float p2[4], t2[4];
        if (y + 1 < HH) {
            float4 pv = *reinterpret_cast<const float4*>(pimg + (y + 1) * WW + c);
            float4 tv = *reinterpret_cast<const float4*>(timg + (y + 1) * WW + c);
            p2[0] = sigm_fast(pv.x); p2[1] = sigm_fast(pv.y);
            p2[2] = sigm_fast(pv.z); p2[3] = sigm_fast(pv.w);
            t2[0] = tv.x; t2[1] = tv.y; t2[2] = tv.z; t2[3] = tv.w;
        } else {
#pragma unroll
            for (int i = 0; i < 4; i++) { p2[i] = 0.f; t2[i] = 0.f; }
        }
#pragma unroll
        for (int i = 0; i < 4; i++) d2[i] = p2[i] - t2[i];

        float VcL = 0.f, VcR = 0.f;
        if (isL) {
            float dl2 = (y + 1 < HH)
                ? sigm_fast(pimg[(y + 1) * WW + c - 1]) - timg[(y + 1) * WW + c - 1] : 0.f;
            VcL = dl0 + dl1 + dl2; dl0 = dl1; dl1 = dl2;
        }
        if (isR) {
            float dr2 = (y + 1 < HH)
                ? sigm_fast(pimg[(y + 1) * WW + c + 4]) - timg[(y + 1) * WW + c + 4] : 0.f;
            VcR = dr0 + dr1 + dr2; dr0 = dr1; dr1 = dr2;
        }

        float V[4];
#pragma unroll
        for (int i = 0; i < 4; i++) V[i] = d0[i] + d1[i] + d2[i];
        float Vlm = __shfl_up_sync(0xFFFFFFFFu, V[3], 1);   if (lane == 0)  Vlm = VcL;
        float Vrp = __shfl_down_sync(0xFFFFFFFFu, V[0], 1); if (lane == 31) Vrp = VcR;
        float H[4];
        H[0] = Vlm + V[0] + V[1];
        H[1] = V[0] + V[1] + V[2];
        H[2] = V[1] + V[2] + V[3];
        H[3] = V[2] + V[3] + Vrp;

        uint32_t bpw = 0, btw = 0;
#pragma unroll
        for (int i = 0; i < 4; i++) {
            float p = p1[i], t = t1[i];
            bool bp = (p > 0.5f);
            bool bt = (t > 0.5f);
            bpw |= ((uint32_t)bp) << (8 * i);
            btw |= ((uint32_t)bt) << (8 * i);

            a0 += p; a1 += t; a2 += p * t;

            float pc = fminf(fmaxf(p, 1e-6f), 1.0f - 1e-6f);
            bool one = (t == 1.0f);
            float pt = one ? pc : (1.0f - pc);
            float bce = -__logf(pt);
            float fw = (1.0f - pt) * (1.0f - pt);
            float at = one ? 0.25f : 0.75f;
            a3 += at * fw * bce;

            float v = H[i] * (1.0f / 9.0f);
            if (bt) { a4 += v * v; a5 += 1.0f; }
        }
        bP32[y * WPR + (c >> 2)] = bpw;
        bT32[y * WPR + (c >> 2)] = btw;

#pragma unroll
        for (int i = 0; i < 4; i++) {
            d0[i] = d1[i]; d1[i] = d2[i];
            p1[i] = p2[i]; t1[i] = t2[i];
        }
    }

    float vals[6] = {a0, a1, a2, a3, a4, a5};
#pragma unroll
    for (int q = 0; q < 6; q++) {
        float v = vals[q];
#pragma unroll
        for (int o = 16; o > 0; o >>= 1) v += __shfl_xor_sync(0xFFFFFFFFu, v, o);
        if (lane == 0) smw[warp * 6 + q] = v;
    }
    __syncthreads();
    int bid = blockIdx.z * gridDim.y + blockIdx.y;
    if (tid < 6) {
        double s = 0.0;
        for (int w = 0; w < 8; w++) s += (double)smw[w * 6 + tid];
        g_partA[tid * NBLK_A + bid] = s;
    }
    __threadfence();
    __syncthreads();
    if (tid == 0) {
        unsigned int old = atomicInc(&g_cntA, NBLK_A - 1);
        lastBlk = (old == NBLK_A - 1);
    }
    __syncthreads();
    if (lastBlk) {
        for (int q = 0; q < 6; q++) {
            double s = 0.0;
            for (int i = tid; i < NBLK_A; i += 256) s += g_partA[q * NBLK_A + i];
            smd[tid] = s; __syncthreads();
            for (int st = 128; st > 0; st >>= 1) {
                if (tid < st) smd[tid] += smd[tid + st];
                __syncthreads();
            }
            if (tid == 0) g_sums[q] = smd[0];
            __syncthreads();
        }
        if (tid == 0) {   // folded init of iteration state (pre-iter2Kernel)
            g_currA[0] = g_currA[1] = 0ULL;
            g_currB[0] = g_currB[1] = 0ULL;
            g_prev[0] = g_prev[1] = 0xFFFFFFFFFFFFFFFFULL;
            g_done[0] = g_done[1] = 0;
            g_last[0] = g_last[1] = 1;
        }
    }
}

// ---------------- skeleton: TWO erosion steps per launch ---------------------
// state closed over {0,1,2}: e = (sum3x3 >= 9); out = e ? (c==1 ? 2 : 1) : 0
// Phase A: gmem->regs sweep (rows r0-1 .. r0+32), results to smem(+gmem w0).
// Phase B: smem->gmem sweep for rows r0 .. r0+31 (halo ±1 entirely in smem).
// Sequential convergence checks for both steps run in the last-arriver.
__device__ __forceinline__ void iter2Arrive(int dstB) {
    __threadfence();
    unsigned int old = atomicInc(&g_cntI, GRID_I2 - 1);
    if (old == GRID_I2 - 1) {
        for (int w = 0; w < 2; w++) {
            if (!g_done[w]) {
                if (g_currA[w] == g_prev[w]) {          // converged at step A
                    g_done[w] = 1; g_last[w] = 0;
                } else {
                    g_prev[w] = g_currA[w];
                    if (g_currB[w] == g_prev[w]) {      // converged at step B
                        g_done[w] = 1; g_last[w] = dstB;
                    } else {
                        g_prev[w] = g_currB[w]; g_last[w] = dstB;
                    }
                }
            }
            g_currA[w] = 0ULL; g_currB[w] = 0ULL;
        }
    }
}

__device__ __forceinline__ uint32_t erodeWord(uint32_t H, uint32_t c) {
    uint32_t ge = __vcmpgeu4(H, 0x09090909u);
    return (ge & 0x01010101u) + (ge & __vcmpeq4(c, 0x01010101u) & 0x01010101u);
}

__global__ __launch_bounds__(256) void iter2Kernel(int srcSel, int dstB) {
    __shared__ uint4 sA4[34 * 64];      // 34 rows x 256 words (34816 B)
    __shared__ int smi[8];
    uint32_t* sA = (uint32_t*)sA4;

    const int tid = threadIdx.x;
    const int z = blockIdx.z;            // 0..31: 0..15 P, 16..31 T
    const int which = z >> 4;
    const int img = z & 15;

    if (g_done[which]) {
        if (tid == 0) iter2Arrive(dstB);
        return;
    }

    const int strip = blockIdx.x;        // output rows [strip*32, +32)
    const int r0 = strip * 32;
    const int g = tid >> 6;              // 0..3
    const int j = tid & 63;              // uint4 column
    const int lane = tid & 31;
    const bool needL = (lane == 0) && (j > 0);
    const bool needR = (lane == 31) && (j < WPR4 - 1);

    const uint32_t* inw;
    uint32_t* outA;
    uint32_t* outB;
    if (which == 0) {
        inw = (srcSel == 0) ? g_binP : ((srcSel == 1) ? g_wp1 : g_wp2);
        outA = g_wp0;
        outB = (dstB == 1) ? g_wp1 : g_wp2;
    } else {
        inw = (srcSel == 0) ? g_binT : ((srcSel == 1) ? g_wt1 : g_wt2);
        outA = g_wt0;
        outB = (dstB == 1) ? g_wt1 : g_wt2;
    }
    inw += (size_t)img * (HH * WPR);
    outA += (size_t)img * (HH * WPR);
    outB += (size_t)img * (HH * WPR);
    const uint4* in4 = (const uint4*)inw;
    uint4* outA4 = (uint4*)outA;
    uint4* outB4 = (uint4*)outB;

    // ---- phase A: k in [k0, kEnd) where k = row - (r0-1), chunked per group --
    const int k0 = 9 * g;
    const int kEnd = (g == 3) ? 34 : k0 + 9;
    {
        const int y0 = r0 - 1 + k0;
        uint4 i0 = make_uint4(0u, 0u, 0u, 0u), i1 = make_uint4(0u, 0u, 0u, 0u);
        if (y0 - 1 >= 0 && y0 - 1 < HH) i0 = in4[(y0 - 1) * WPR4 + j];
        if (y0 >= 0 && y0 < HH)         i1 = in4[y0 * WPR4 + j];
        uint32_t l0 = 0, l1 = 0, q0 = 0, q1 = 0;
        if (needL) {
            if (y0 - 1 >= 0 && y0 - 1 < HH) l0 = inw[(y0 - 1) * WPR + 4 * j - 1];
            if (y0 >= 0 && y0 < HH)         l1 = inw[y0 * WPR + 4 * j - 1];
        }
        if (needR) {
            if (y0 - 1 >= 0 && y0 - 1 < HH) q0 = inw[(y0 - 1) * WPR + 4 * j + 4];
            if (y0 >= 0 && y0 < HH)         q1 = inw[y0 * WPR + 4 * j + 4];
        }

        int accA = 0;
        for (int k = k0; k < kEnd; k++) {
            const int y = r0 - 1 + k;
            uint4 i2 = make_uint4(0u, 0u, 0u, 0u);
            if (y + 1 < HH && y + 1 >= 0) i2 = in4[(y + 1) * WPR4 + j];
            uint32_t l2 = 0, q2 = 0;
            if (needL && y + 1 < HH && y + 1 >= 0) l2 = inw[(y + 1) * WPR + 4 * j - 1];
            if (needR && y + 1 < HH && y + 1 >= 0) q2 = inw[(y + 1) * WPR + 4 * j + 4];

            uint32_t Vx = i0.x + i1.x + i2.x;
            uint32_t Vy = i0.y + i1.y + i2.y;
            uint32_t Vz = i0.z + i1.z + i2.z;
            uint32_t Vw = i0.w + i1.w + i2.w;
            uint32_t VL = __shfl_up_sync(0xFFFFFFFFu, Vw, 1);
            if (lane == 0) VL = l0 + l1 + l2;
            uint32_t VR = __shfl_down_sync(0xFFFFFFFFu, Vx, 1);
            if (lane == 31) VR = q0 + q1 + q2;

            uint4 o;
            o.x = erodeWord(Vx + ((Vx >> 8) | (Vy << 24)) + ((Vx << 8) | (VL >> 24)), i1.x);
            o.y = erodeWord(Vy + ((Vy >> 8) | (Vz << 24)) + ((Vy << 8) | (Vx >> 24)), i1.y);
            o.z = erodeWord(Vz + ((Vz >> 8) | (Vw << 24)) + ((Vz << 8) | (Vy >> 24)), i1.z);
            o.w = erodeWord(Vw + ((Vw >> 8) | (VR << 24)) + ((Vw << 8) | (Vz >> 24)), i1.w);

            sA4[k * WPR4 + j] = o;
            if (k >= 1 && k <= 32) {
                outA4[y * WPR4 + j] = o;
                accA = __dp4a(o.x, 0x01010101u, (unsigned int)accA);
                accA = __dp4a(o.y, 0x01010101u, (unsigned int)accA);
                accA = __dp4a(o.z, 0x01010101u, (unsigned int)accA);
                accA = __dp4a(o.w, 0x01010101u, (unsigned int)accA);
            }
            i0 = i1; i1 = i2;
            l0 = l1; l1 = l2; q0 = q1; q1 = q2;
        }

        // block-reduce accA
#pragma unroll
        for (int o = 16; o > 0; o >>= 1) accA += __shfl_xor_sync(0xFFFFFFFFu, accA, o);
        if (lane == 0) smi[tid >> 5] = accA;
    }
    __syncthreads();                     // smem A complete + accA staged
    if (tid == 0) {
        int s = 0;
        for (int w = 0; w < 8; w++) s += smi[w];
        atomicAdd(&g_currA[which], (unsigned long long)s);
    }

    // ---- phase B: rows r0+8g .. r0+8g+7, halo entirely from smem -------------
    {
        const int kk = 8 * g + 1;
        uint4 a0 = sA4[(kk - 1) * WPR4 + j];
        uint4 a1 = sA4[kk * WPR4 + j];
        uint32_t l0 = (j > 0) ? sA[(kk - 1) * WPR + 4 * j - 1] : 0u;
        uint32_t l1 = (j > 0) ? sA[kk * WPR + 4 * j - 1] : 0u;
        uint32_t q0 = (j < 63) ? sA[(kk - 1) * WPR + 4 * j + 4] : 0u;
        uint32_t q1 = (j < 63) ? sA[kk * WPR + 4 * j + 4] : 0u;

        int accB = 0;
#pragma unroll
        for (int m = 0; m < 8; m++) {
            const int k = kk + m;
            uint4 a2 = sA4[(k + 1) * WPR4 + j];
            uint32_t l2 = (j > 0) ? sA[(k + 1) * WPR + 4 * j - 1] : 0u;
            uint32_t q2 = (j < 63) ? sA[(k + 1) * WPR + 4 * j + 4] : 0u;

            uint32_t Vx = a0.x + a1.x + a2.x;
            uint32_t Vy = a0.y + a1.y + a2.y;
            uint32_t Vz = a0.z + a1.z + a2.z;
            uint32_t Vw = a0.w + a1.w + a2.w;
            uint32_t VL = l0 + l1 + l2;
            uint32_t VR = q0 + q1 + q2;

            uint4 o;
            o.x = erodeWord(Vx + ((Vx >> 8) | (Vy << 24)) + ((Vx << 8) | (VL >> 24)), a1.x);
            o.y = erodeWord(Vy + ((Vy >> 8) | (Vz << 24)) + ((Vy << 8) | (Vx >> 24)), a1.y);
            o.z = erodeWord(Vz + ((Vz >> 8) | (Vw << 24)) + ((Vz << 8) | (Vy >> 24)), a1.z);
            o.w = erodeWord(Vw + ((Vw >> 8) | (VR << 24)) + ((Vw << 8) | (Vz >> 24)), a1.w);

            outB4[(r0 + 8 * g + m) * WPR4 + j] = o;
            accB = __dp4a(o.x, 0x01010101u, (unsigned int)accB);
            accB = __dp4a(o.y, 0x01010101u, (unsigned int)accB);
            accB = __dp4a(o.z, 0x01010101u, (unsigned int)accB);
            accB = __dp4a(o.w, 0x01010101u, (unsigned int)accB);

            a0 = a1; a1 = a2;
            l0 = l1; l1 = l2; q0 = q1; q1 = q2;
        }

#pragma unroll
        for (int o = 16; o > 0; o >>= 1) accB += __shfl_xor_sync(0xFFFFFFFFu, accB, o);
        __syncthreads();                 // protect smi reuse
        if (lane == 0) smi[tid >> 5] = accB;
    }
    __syncthreads();
    if (tid == 0) {
        int s = 0;
        for (int w = 0; w < 8; w++) s += smi[w];
        atomicAdd(&g_currB[which], (unsigned long long)s);
        iter2Arrive(dstB);
    }
}

// ---------------- finalize: SWAR Sobel + skeleton dice (register sweep) ------
// Binary input => |gx|,|gy| <= 4; f = clip(skel + .5*sqrt(gx^2+gy^2+1e-8),0,1)
// quantizes: f = 1 if skel>=1 or g2>=4 else {0:5e-5, 1:.5, 2:.7071}[g2]
__global__ __launch_bounds__(256) void finKernel(float* __restrict__ out) {
    __shared__ float smw[24];
    __shared__ double smd[256];
    __shared__ double S3[3];
    __shared__ bool lastBlk;

    const int img = blockIdx.z;
    const int tid = threadIdx.x;
    const int lane = tid & 31, warp = tid >> 5;
    const int col = warp * 32 + lane;
    const int by = blockIdx.y * 16;

    const uint32_t* bP = g_binP + (size_t)img * (HH * WPR);
    const uint32_t* bT = g_binT + (size_t)img * (HH * WPR);
    const int lp = g_last[0], lt = g_last[1];
    const uint32_t* sp = ((lp == 0) ? g_wp0 : ((lp == 1) ? g_wp1 : g_wp2)) + (size_t)img * (HH * WPR);
    const uint32_t* st = ((lt == 0) ? g_wt0 : ((lt == 1) ? g_wt1 : g_wt2)) + (size_t)img * (HH * WPR);

    const bool isL = (lane == 0) && (col > 0);
    const bool isR = (lane == 31) && (col < WPR - 1);

    uint32_t p0 = (by > 0) ? bP[(by - 1) * WPR + col] : 0u;
    uint32_t p1 = bP[by * WPR + col];
    uint32_t t0 = (by > 0) ? bT[(by - 1) * WPR + col] : 0u;
    uint32_t t1 = bT[by * WPR + col];
    uint32_t lp0 = 0, lp1 = 0, lt0 = 0, lt1 = 0, rp0 = 0, rp1 = 0, rt0 = 0, rt1 = 0;
    if (isL) {
        lp0 = (by > 0) ? bP[(by - 1) * WPR + col - 1] : 0u; lp1 = bP[by * WPR + col - 1];
        lt0 = (by > 0) ? bT[(by - 1) * WPR + col - 1] : 0u; lt1 = bT[by * WPR + col - 1];
    }
    if (isR) {
        rp0 = (by > 0) ? bP[(by - 1) * WPR + col + 1] : 0u; rp1 = bP[by * WPR + col + 1];
        rt0 = (by > 0) ? bT[(by - 1) * WPR + col + 1] : 0u; rt1 = bT[by * WPR + col + 1];
    }

    float a0 = 0.f, a1 = 0.f, a2 = 0.f;
#pragma unroll 4
    for (int y = by; y < by + 16; y++) {
        uint32_t p2 = (y + 1 < HH) ? bP[(y + 1) * WPR + col] : 0u;
        uint32_t t2 = (y + 1 < HH) ? bT[(y + 1) * WPR + col] : 0u;
        uint32_t A_P = p0 + p1 + p1 + p2, B_P = p2 + (0x01010101u - p0);
        uint32_t A_T = t0 + t1 + t1 + t2, B_T = t2 + (0x01010101u - t0);

        uint32_t eAlP = 0u, eBlP = 0x01010101u, eAlT = 0u, eBlT = 0x01010101u;
        uint32_t eArP = 0u, eBrP = 0x01010101u, eArT = 0u, eBrT = 0x01010101u;
        if (isL) {
            uint32_t lp2 = (y + 1 < HH) ? bP[(y + 1) * WPR + col - 1] : 0u;
            uint32_t lt2 = (y + 1 < HH) ? bT[(y + 1) * WPR + col - 1] : 0u;
            eAlP = lp0 + lp1 + lp1 + lp2; eBlP = lp2 + (0x01010101u - lp0);
            eAlT = lt0 + lt1 + lt1 + lt2; eBlT = lt2 + (0x01010101u - lt0);
            lp0 = lp1; lp1 = lp2; lt0 = lt1; lt1 = lt2;
        }
        if (isR) {
            uint32_t rp2 = (y + 1 < HH) ? bP[(y + 1) * WPR + col + 1] : 0u;
            uint32_t rt2 = (y + 1 < HH) ? bT[(y + 1) * WPR + col + 1] : 0u;
            eArP = rp0 + rp1 + rp1 + rp2; eBrP = rp2 + (0x01010101u - rp0);
            eArT = rt0 + rt1 + rt1 + rt2; eBrT = rt2 + (0x01010101u - rt0);
            rp0 = rp1; rp1 = rp2; rt0 = rt1; rt1 = rt2;
        }

        uint32_t AlP = __shfl_up_sync(0xFFFFFFFFu, A_P, 1);   if (lane == 0)  AlP = eAlP;
        uint32_t ArP = __shfl_down_sync(0xFFFFFFFFu, A_P, 1); if (lane == 31) ArP = eArP;
        uint32_t BlP = __shfl_up_sync(0xFFFFFFFFu, B_P, 1);   if (lane == 0)  BlP = eBlP;
        uint32_t BrP = __shfl_down_sync(0xFFFFFFFFu, B_P, 1); if (lane == 31) BrP = eBrP;
        uint32_t AlT = __shfl_up_sync(0xFFFFFFFFu, A_T, 1);   if (lane == 0)  AlT = eAlT;
        uint32_t ArT = __shfl_down_sync(0xFFFFFFFFu, A_T, 1); if (lane == 31) ArT = eArT;
        uint32_t BlT = __shfl_up_sync(0xFFFFFFFFu, B_T, 1);   if (lane == 0)  BlT = eBlT;
        uint32_t BrT = __shfl_down_sync(0xFFFFFFFFu, B_T, 1); if (lane == 31) BrT = eBrT;

        uint32_t HxP = ((A_P >> 8) | (ArP << 24)) + (0x04040404u - ((A_P << 8) | (AlP >> 24)));
        uint32_t HyP = ((B_P << 8) | (BlP >> 24)) + B_P + B_P + ((B_P >> 8) | (BrP << 24));
        uint32_t HxT = ((A_T >> 8) | (ArT << 24)) + (0x04040404u - ((A_T << 8) | (AlT >> 24)));
        uint32_t HyT = ((B_T << 8) | (BlT >> 24)) + B_T + B_T + ((B_T >> 8) | (BrT << 24));

        uint32_t SP = sp[y * WPR + col];
        uint32_t ST = st[y * WPR + col];

#pragma unroll
        for (int b = 0; b < 4; b++) {
            int s = 8 * b;
            int gxp = (int)((HxP >> s) & 0xFF) - 4;
            int gyp = (int)((HyP >> s) & 0xFF) - 4;
            int g2p = gxp * gxp + gyp * gyp;
            int skp = (int)((SP >> s) & 0xFF);
            float fP = (skp | (g2p >= 4)) ? 1.0f
                     : (g2p == 0 ? 5.0e-5f : (g2p == 1 ? 0.5f : 0.70710678f));

            int gxt = (int)((HxT >> s) & 0xFF) - 4;
            int gyt = (int)((HyT >> s) & 0xFF) - 4;
            int g2t = gxt * gxt + gyt * gyt;
            int skt = (int)((ST >> s) & 0xFF);
            float fT = (skt | (g2t >= 4)) ? 1.0f
                     : (g2t == 0 ? 5.0e-5f : (g2t == 1 ? 0.5f : 0.70710678f));

            a0 += fP; a1 += fT; a2 += fP * fT;
        }
        p0 = p1; p1 = p2; t0 = t1; t1 = t2;
    }

    float vals[3] = {a0, a1, a2};
#pragma unroll
    for (int q = 0; q < 3; q++) {
        float v = vals[q];
#pragma unroll
        for (int o = 16; o > 0; o >>= 1) v += __shfl_xor_sync(0xFFFFFFFFu, v, o);
        if (lane == 0) smw[warp * 3 + q] = v;
    }
    __syncthreads();
    int bid = blockIdx.z * gridDim.y + blockIdx.y;
    if (tid < 3) {
        double sm = 0.0;
        for (int w = 0; w < 8; w++) sm += (double)smw[w * 3 + tid];
        g_partF[tid * NBLK_F + bid] = sm;
    }
    __threadfence();
    __syncthreads();
    if (tid == 0) {
        unsigned int old = atomicInc(&g_cntF, NBLK_F - 1);
        lastBlk = (old == NBLK_F - 1);
    }
    __syncthreads();
    if (lastBlk) {
        for (int q = 0; q < 3; q++) {
            double s = 0.0;
            for (int i = tid; i < NBLK_F; i += 256) s += g_partF[q * NBLK_F + i];
            smd[tid] = s; __syncthreads();
            for (int stp = 128; stp > 0; stp >>= 1) {
                if (tid < stp) smd[tid] += smd[tid + stp];
                __syncthreads();
            }
            if (tid == 0) S3[q] = smd[0];
            __syncthreads();
        }
        if (tid == 0) {
            double Sp = g_sums[0], St = g_sums[1], Spt = g_sums[2];
            double Sf = g_sums[3], Sc = g_sums[4], nw = g_sums[5];
            double S6 = S3[0], S7 = S3[1], S8 = S3[2];

            double skel_dice = (2.0 * S8 + 1.0) / (S6 + S7 + 1.0);
            double skeleton = 1.0 - skel_dice;
            double dice = 1.0 - (2.0 * Spt + 1.0) / (Sp + St + 1.0);
            double focal = Sf / (double)NPIX;
            focal = fmin(fmax(focal, 0.0), 10.0);
            double conn = (nw == 0.0) ? 0.0 : (Sc / fmax(nw, 1.0));

            double total = 0.3 * skeleton + 0.4 * dice + 0.2 * focal + 0.1 * conn;
            if (isnan(total) || isinf(total)) total = dice;
            out[0] = (float)total;
        }
    }
}

// ---------------- launch -----------------------------------------------------
extern "C" void kernel_launch(void* const* d_in, const int* in_sizes, int n_in,
                              void* d_out, int out_size) {
    const float* pred = (const float*)d_in[0];
    const float* target = (const float*)d_in[1];
    float* out = (float*)d_out;

    dim3 blk(256);
    dim3 grdA(1, 64, 16);    // full-width x 16-row strips, batch
    dim3 grdI(32, 1, 32);    // 32 row-strips of 32; z: 0..15 P, 16..31 T
    dim3 grdF(1, 64, 16);    // full-width x 16-row strips, batch

    mainKernel<<<grdA, blk>>>(pred, target);

    // 5 double-step launches cover the reference's 10 iterations
    for (int i = 0; i < 5; i++) {
        int srcSel = (i == 0) ? 0 : ((i & 1) ? 1 : 2);  // 0=bin, 1=w1, 2=w2
        int dstB = (i & 1) ? 2 : 1;
        iter2Kernel<<<grdI, blk>>>(srcSel, dstB);
    }

    finKernel<<<grdF, blk>>>(out);
}